// round 5
// baseline (speedup 1.0000x reference)
#include <cuda_runtime.h>
#include <math.h>

// Problem constants
#define B_  2
#define T_  2048
#define C_  1024
#define H_  16
#define D_  64
#define M_  (B_ * T_)        // 4096 rows
#define QKV_N (3 * C_)       // 3072

// Scratch (allocation-free rule: __device__ globals)
__device__ float g_qkv[(size_t)M_ * QKV_N];   // [B,T,3C]
__device__ float g_attn[(size_t)M_ * C_];     // [B,T,C]

__device__ __forceinline__ unsigned f2tf32(float f) {
    unsigned u;
    asm("cvt.rna.tf32.f32 %0, %1;" : "=r"(u) : "f"(f));
    return u;
}
__device__ __forceinline__ unsigned smem_u32(const void* p) {
    return (unsigned)__cvta_generic_to_shared(p);
}
#define CP_ASYNC16(dst, src) \
    asm volatile("cp.async.cg.shared.global [%0], [%1], 16;" \
                 :: "r"(dst), "l"(src))
#define CP_COMMIT()  asm volatile("cp.async.commit_group;")
#define CP_WAIT1()   asm volatile("cp.async.wait_group 1;")

// ---------------------------------------------------------------------------
// TF32 tensor-core GEMM with bias, 3-stage cp.async pipeline.
// BM=BN=128, BK=16; 256 threads = 8 warps (2x4); warp does 64x32 via
// 4x4 m16n8k8 mma. fp32 staged in smem, tf32 convert at fragment load.
// One __syncthreads per k-iter.
// ---------------------------------------------------------------------------
#define A_STAGE (128 * 20)
#define B_STAGE (16 * 136)
#define GEMM_SMEM_BYTES (3 * (A_STAGE + B_STAGE) * 4)

__global__ __launch_bounds__(256) void gemm_tf32_kernel(
        const float* __restrict__ A,
        const float* __restrict__ Bm,
        const float* __restrict__ bias,
        float* __restrict__ Cm,
        int M, int N, int K) {
    extern __shared__ float gsm[];
    float* As = gsm;                    // [3][128][20]
    float* Bs = gsm + 3 * A_STAGE;      // [3][16][136]

    const int tid  = threadIdx.x;
    const int lane = tid & 31;
    const int warp = tid >> 5;
    const int warpRow = warp >> 2;
    const int warpCol = warp & 3;
    const int group = lane >> 2;
    const int tid4  = lane & 3;

    const int brow = blockIdx.y * 128;
    const int bcol = blockIdx.x * 128;

    auto issue = [&](int s, int k0) {
        #pragma unroll
        for (int i = 0; i < 2; i++) {
            int idx = tid + i * 256;                 // 0..511
            int row = idx >> 2, kq = idx & 3;        // A: 128r x 4 quads
            CP_ASYNC16(smem_u32(&As[s * A_STAGE + row * 20 + kq * 4]),
                       &A[(size_t)(brow + row) * K + k0 + kq * 4]);
            int kb = idx >> 5, cq = idx & 31;        // B: 16k x 32 quads
            CP_ASYNC16(smem_u32(&Bs[s * B_STAGE + kb * 136 + cq * 4]),
                       &Bm[(size_t)(k0 + kb) * N + bcol + cq * 4]);
        }
    };

    float acc[4][4][4];
    #pragma unroll
    for (int i = 0; i < 4; i++)
        #pragma unroll
        for (int j = 0; j < 4; j++)
            #pragma unroll
            for (int r = 0; r < 4; r++) acc[i][j][r] = 0.f;

    issue(0, 0);  CP_COMMIT();
    issue(1, 16); CP_COMMIT();

    const int nIter = K / 16;
    for (int it = 0; it < nIter; it++) {
        CP_WAIT1();           // stage it%3 landed (this thread's groups)
        __syncthreads();      // ...and everyone's; everyone past compute it-1
        if (it + 2 < nIter) issue((it + 2) % 3, (it + 2) * 16);
        CP_COMMIT();          // uniform group count (possibly empty)

        const float* as = &As[(it % 3) * A_STAGE];
        const float* bs = &Bs[(it % 3) * B_STAGE];

        #pragma unroll
        for (int ks = 0; ks < 2; ks++) {
            int k = ks * 8;
            unsigned a[4][4];
            #pragma unroll
            for (int mt = 0; mt < 4; mt++) {
                int row = warpRow * 64 + mt * 16 + group;
                a[mt][0] = f2tf32(as[(row    ) * 20 + k + tid4    ]);
                a[mt][1] = f2tf32(as[(row + 8) * 20 + k + tid4    ]);
                a[mt][2] = f2tf32(as[(row    ) * 20 + k + tid4 + 4]);
                a[mt][3] = f2tf32(as[(row + 8) * 20 + k + tid4 + 4]);
            }
            unsigned b[4][2];
            #pragma unroll
            for (int nt = 0; nt < 4; nt++) {
                int col = warpCol * 32 + nt * 8 + group;
                b[nt][0] = f2tf32(bs[(k + tid4    ) * 136 + col]);
                b[nt][1] = f2tf32(bs[(k + tid4 + 4) * 136 + col]);
            }
            #pragma unroll
            for (int mt = 0; mt < 4; mt++)
                #pragma unroll
                for (int nt = 0; nt < 4; nt++) {
                    asm volatile(
                        "mma.sync.aligned.m16n8k8.row.col.f32.tf32.tf32.f32 "
                        "{%0,%1,%2,%3},{%4,%5,%6,%7},{%8,%9},{%0,%1,%2,%3};"
                        : "+f"(acc[mt][nt][0]), "+f"(acc[mt][nt][1]),
                          "+f"(acc[mt][nt][2]), "+f"(acc[mt][nt][3])
                        : "r"(a[mt][0]), "r"(a[mt][1]),
                          "r"(a[mt][2]), "r"(a[mt][3]),
                          "r"(b[nt][0]), "r"(b[nt][1]));
                }
        }
    }

    #pragma unroll
    for (int mt = 0; mt < 4; mt++) {
        int m0 = brow + warpRow * 64 + mt * 16 + group;
        #pragma unroll
        for (int nt = 0; nt < 4; nt++) {
            int n0 = bcol + warpCol * 32 + nt * 8 + tid4 * 2;
            Cm[(size_t)m0 * N + n0    ] = acc[mt][nt][0] + bias[n0];
            Cm[(size_t)m0 * N + n0 + 1] = acc[mt][nt][1] + bias[n0 + 1];
            Cm[(size_t)(m0 + 8) * N + n0    ] = acc[mt][nt][2] + bias[n0];
            Cm[(size_t)(m0 + 8) * N + n0 + 1] = acc[mt][nt][3] + bias[n0 + 1];
        }
    }
}

// ---------------------------------------------------------------------------
// Tensor-core flash attention (causal, tf32 mma).
// Block = (128-row q-tile, head, batch); 256 threads = 8 warps x 16 Q-rows.
// K/V streamed in 64-row tiles; warps whose rows are entirely above the
// causal boundary skip the tile. Smem stride 68 => conflict-free fragments.
// ---------------------------------------------------------------------------
#define AST 68
#define QROWS 128
#define ATTN_SMEM_BYTES ((QROWS + 64 + 64 + QROWS) * AST * 4)

__global__ __launch_bounds__(256) void attn_tc_kernel(
        const float* __restrict__ qkv,
        float* __restrict__ out) {
    int qt = blockIdx.x;
    int h  = blockIdx.y;
    int b  = blockIdx.z;

    extern __shared__ unsigned smu[];
    unsigned* Qs = smu;                      // 128 x AST
    unsigned* Ks = Qs + QROWS * AST;         // 64 x AST
    unsigned* Vs = Ks + 64 * AST;            // 64 x AST
    unsigned* Ps = Vs + 64 * AST;            // 128 x AST

    const int tid  = threadIdx.x;
    const int lane = tid & 31;
    const int warp = tid >> 5;               // 0..7
    const int g = lane >> 2;
    const int t = lane & 3;
    const int m0 = warp * 16;                // warp's Q-row base in tile

    const float scale = 0.125f;
    const float* base = qkv + (size_t)b * T_ * QKV_N;
    const int q0 = qt * QROWS;
    const int hoff = h * D_;

    // Load Q tile (scale folded, tf32): 128 rows x 16 quads
    for (int i = tid; i < QROWS * 16; i += 256) {
        int r = i >> 4, q = i & 15;
        float4 v = *reinterpret_cast<const float4*>(
            &base[(size_t)(q0 + r) * QKV_N + hoff + q * 4]);
        unsigned* dst = &Qs[r * AST + q * 4];
        dst[0] = f2tf32(v.x * scale);
        dst[1] = f2tf32(v.y * scale);
        dst[2] = f2tf32(v.z * scale);
        dst[3] = f2tf32(v.w * scale);
    }

    float o[8][4];
    #pragma unroll
    for (int d = 0; d < 8; d++)
        #pragma unroll
        for (int r = 0; r < 4; r++) o[d][r] = 0.f;
    float mRow[2] = {-INFINITY, -INFINITY};
    float lRow[2] = {0.f, 0.f};

    __syncthreads();

    const int ktMax = 2 * qt + 1;
    for (int kt = 0; kt <= ktMax; kt++) {
        int k0 = kt * 64;
        // Load K, V tiles (tf32): 64 rows x 16 quads
        for (int i = tid; i < 64 * 16; i += 256) {
            int r = i >> 4, q = i & 15;
            size_t rowbase = (size_t)(k0 + r) * QKV_N + hoff + q * 4;
            float4 kv = *reinterpret_cast<const float4*>(&base[rowbase + C_]);
            float4 vv = *reinterpret_cast<const float4*>(&base[rowbase + 2 * C_]);
            unsigned* dk = &Ks[r * AST + q * 4];
            dk[0] = f2tf32(kv.x); dk[1] = f2tf32(kv.y);
            dk[2] = f2tf32(kv.z); dk[3] = f2tf32(kv.w);
            unsigned* dv = &Vs[r * AST + q * 4];
            dv[0] = f2tf32(vv.x); dv[1] = f2tf32(vv.y);
            dv[2] = f2tf32(vv.z); dv[3] = f2tf32(vv.w);
        }
        __syncthreads();

        // Skip tiles entirely above this warp's causal boundary
        if (k0 <= q0 + m0 + 15) {
            // ---- S = Q @ K^T ----
            float s[8][4];
            #pragma unroll
            for (int n = 0; n < 8; n++)
                #pragma unroll
                for (int r = 0; r < 4; r++) s[n][r] = 0.f;

            #pragma unroll
            for (int kk = 0; kk < 8; kk++) {
                unsigned a0 = Qs[(m0 + g    ) * AST + kk * 8 + t    ];
                unsigned a1 = Qs[(m0 + g + 8) * AST + kk * 8 + t    ];
                unsigned a2 = Qs[(m0 + g    ) * AST + kk * 8 + t + 4];
                unsigned a3 = Qs[(m0 + g + 8) * AST + kk * 8 + t + 4];
                #pragma unroll
                for (int n = 0; n < 8; n++) {
                    unsigned b0 = Ks[(n * 8 + g) * AST + kk * 8 + t    ];
                    unsigned b1 = Ks[(n * 8 + g) * AST + kk * 8 + t + 4];
                    asm volatile(
                        "mma.sync.aligned.m16n8k8.row.col.f32.tf32.tf32.f32 "
                        "{%0,%1,%2,%3},{%4,%5,%6,%7},{%8,%9},{%0,%1,%2,%3};"
                        : "+f"(s[n][0]), "+f"(s[n][1]),
                          "+f"(s[n][2]), "+f"(s[n][3])
                        : "r"(a0), "r"(a1), "r"(a2), "r"(a3),
                          "r"(b0), "r"(b1));
                }
            }

            // ---- causal mask (global indices) where tile crosses diagonal
            if (k0 + 63 > q0 + m0) {
                int r0 = q0 + m0 + g, r1 = r0 + 8;
                #pragma unroll
                for (int n = 0; n < 8; n++) {
                    int c0 = k0 + n * 8 + 2 * t;
                    if (c0     > r0) s[n][0] = -INFINITY;
                    if (c0 + 1 > r0) s[n][1] = -INFINITY;
                    if (c0     > r1) s[n][2] = -INFINITY;
                    if (c0 + 1 > r1) s[n][3] = -INFINITY;
                }
            }

            // ---- online softmax (rows g and g+8) ----
            #pragma unroll
            for (int half = 0; half < 2; half++) {
                float pm = -INFINITY;
                #pragma unroll
                for (int n = 0; n < 8; n++) {
                    pm = fmaxf(pm, s[n][2 * half]);
                    pm = fmaxf(pm, s[n][2 * half + 1]);
                }
                pm = fmaxf(pm, __shfl_xor_sync(0xffffffff, pm, 1));
                pm = fmaxf(pm, __shfl_xor_sync(0xffffffff, pm, 2));

                float mNew = fmaxf(mRow[half], pm);
                float alpha = __expf(mRow[half] - mNew);
                float lsum = 0.f;
                #pragma unroll
                for (int n = 0; n < 8; n++) {
                    float p0 = __expf(s[n][2 * half    ] - mNew);
                    float p1 = __expf(s[n][2 * half + 1] - mNew);
                    s[n][2 * half    ] = p0;
                    s[n][2 * half + 1] = p1;
                    lsum += p0 + p1;
                }
                lsum += __shfl_xor_sync(0xffffffff, lsum, 1);
                lsum += __shfl_xor_sync(0xffffffff, lsum, 2);
                mRow[half] = mNew;
                lRow[half] = lRow[half] * alpha + lsum;
                #pragma unroll
                for (int n = 0; n < 8; n++) {
                    o[n][2 * half    ] *= alpha;
                    o[n][2 * half + 1] *= alpha;
                }
            }

            // ---- P (tf32) to warp-private slice ----
            #pragma unroll
            for (int n = 0; n < 8; n++) {
                int c = n * 8 + 2 * t;
                Ps[(m0 + g    ) * AST + c    ] = f2tf32(s[n][0]);
                Ps[(m0 + g    ) * AST + c + 1] = f2tf32(s[n][1]);
                Ps[(m0 + g + 8) * AST + c    ] = f2tf32(s[n][2]);
                Ps[(m0 + g + 8) * AST + c + 1] = f2tf32(s[n][3]);
            }
            __syncwarp();

            // ---- O += P @ V ----
            #pragma unroll
            for (int kk = 0; kk < 8; kk++) {
                unsigned a0 = Ps[(m0 + g    ) * AST + kk * 8 + t    ];
                unsigned a1 = Ps[(m0 + g + 8) * AST + kk * 8 + t    ];
                unsigned a2 = Ps[(m0 + g    ) * AST + kk * 8 + t + 4];
                unsigned a3 = Ps[(m0 + g + 8) * AST + kk * 8 + t + 4];
                #pragma unroll
                for (int d = 0; d < 8; d++) {
                    unsigned b0 = Vs[(kk * 8 + t    ) * AST + d * 8 + g];
                    unsigned b1 = Vs[(kk * 8 + t + 4) * AST + d * 8 + g];
                    asm volatile(
                        "mma.sync.aligned.m16n8k8.row.col.f32.tf32.tf32.f32 "
                        "{%0,%1,%2,%3},{%4,%5,%6,%7},{%8,%9},{%0,%1,%2,%3};"
                        : "+f"(o[d][0]), "+f"(o[d][1]),
                          "+f"(o[d][2]), "+f"(o[d][3])
                        : "r"(a0), "r"(a1), "r"(a2), "r"(a3),
                          "r"(b0), "r"(b1));
                }
            }
        }
        __syncthreads();
    }

    // ---- epilogue ----
    #pragma unroll
    for (int half = 0; half < 2; half++) {
        float inv = 1.0f / lRow[half];
        int row = q0 + m0 + g + half * 8;
        #pragma unroll
        for (int d = 0; d < 8; d++) {
            int col = hoff + d * 8 + 2 * t;
            out[((size_t)b * T_ + row) * C_ + col    ] = o[d][2 * half    ] * inv;
            out[((size_t)b * T_ + row) * C_ + col + 1] = o[d][2 * half + 1] * inv;
        }
    }
}

// ---------------------------------------------------------------------------
extern "C" void kernel_launch(void* const* d_in, const int* in_sizes, int n_in,
                              void* d_out, int out_size) {
    const float* x     = (const float*)d_in[0];
    const float* Wqkv  = (const float*)d_in[1];
    const float* bqkv  = (const float*)d_in[2];
    const float* Wproj = (const float*)d_in[3];
    const float* bproj = (const float*)d_in[4];
    float* out = (float*)d_out;

    float* qkv  = nullptr;
    float* attn = nullptr;
    cudaGetSymbolAddress((void**)&qkv,  g_qkv);
    cudaGetSymbolAddress((void**)&attn, g_attn);

    cudaFuncSetAttribute(gemm_tf32_kernel,
                         cudaFuncAttributeMaxDynamicSharedMemorySize,
                         GEMM_SMEM_BYTES);
    cudaFuncSetAttribute(attn_tc_kernel,
                         cudaFuncAttributeMaxDynamicSharedMemorySize,
                         ATTN_SMEM_BYTES);

    // 1) QKV projection (tf32 TC, cp.async pipelined)
    {
        dim3 grid(QKV_N / 128, M_ / 128);
        gemm_tf32_kernel<<<grid, 256, GEMM_SMEM_BYTES>>>(
            x, Wqkv, bqkv, qkv, M_, QKV_N, C_);
    }
    // 2) Causal flash attention (tf32 TC, 128-row q-tiles)
    {
        dim3 grid(T_ / QROWS, H_, B_);
        attn_tc_kernel<<<grid, 256, ATTN_SMEM_BYTES>>>(qkv, attn);
    }
    // 3) Output projection
    {
        dim3 grid(C_ / 128, M_ / 128);
        gemm_tf32_kernel<<<grid, 256, GEMM_SMEM_BYTES>>>(
            attn, Wproj, bproj, out, M_, C_, C_);
    }
}

// round 13
// speedup vs baseline: 1.1994x; 1.1994x over previous
#include <cuda_runtime.h>
#include <math.h>

// Problem constants
#define B_  2
#define T_  2048
#define C_  1024
#define H_  16
#define D_  64
#define M_  4096             // B*T
#define QKV_N 3072
#define K_  1024
#define KB_ (K_ / 8)         // 128 k-blocks of 8

// Scratch (allocation-free rule: __device__ globals)
__device__ float g_qkv[(size_t)M_ * QKV_N];    // QKV out (tf32-rounded, row-major)
__device__ float g_attn[(size_t)M_ * C_];      // attention O (fp32, row-major)
__device__ float g_af[(size_t)M_ * C_];        // A-fragments (x, then O)
__device__ float g_wqkvF[(size_t)K_ * QKV_N];  // B-fragments of W_qkv
__device__ float g_wprojF[(size_t)K_ * C_];    // B-fragments of W_proj

// ---------------------------------------------------------------------------
__device__ __forceinline__ unsigned f2tf32(float f) {
    unsigned u;
    asm("cvt.rna.tf32.f32 %0, %1;" : "=r"(u) : "f"(f));
    return u;
}
__device__ __forceinline__ float cvtf(float v) {
    return __uint_as_float(f2tf32(v));
}
__device__ __forceinline__ unsigned smem_u32(const void* p) {
    return (unsigned)__cvta_generic_to_shared(p);
}
#define CP_ASYNC16(dst, src) \
    asm volatile("cp.async.cg.shared.global [%0], [%1], 16;" \
                 :: "r"(dst), "l"(src))
#define CP_COMMIT()  asm volatile("cp.async.commit_group;")
#define CP_WAIT1()   asm volatile("cp.async.wait_group 1;")

// ---------------------------------------------------------------------------
// Prep: row-major [4096,1024] -> A-fragment order (tf32).
// vec4 q -> lane l=q&31 (g=l>>2,t=l&3), kb=(q>>5)%KB_, rb=(q>>5)/KB_:
//   {A[rb16+g][kb8+t], A[rb16+g+8][kb8+t], A[rb16+g][kb8+t+4], A[rb16+g+8][kb8+t+4]}
// ---------------------------------------------------------------------------
__global__ void prep_a_frag(const float* __restrict__ src, float* __restrict__ dst) {
    int q = blockIdx.x * blockDim.x + threadIdx.x;
    if (q >= M_ * K_ / 4) return;
    int l = q & 31;
    int rk = q >> 5;
    int kb = rk % KB_, rb = rk / KB_;
    int g = l >> 2, t = l & 3;
    int r0 = rb * 16 + g, c0 = kb * 8 + t;
    float4 o;
    o.x = cvtf(src[(size_t)r0 * K_ + c0]);
    o.y = cvtf(src[(size_t)(r0 + 8) * K_ + c0]);
    o.z = cvtf(src[(size_t)r0 * K_ + c0 + 4]);
    o.w = cvtf(src[(size_t)(r0 + 8) * K_ + c0 + 4]);
    reinterpret_cast<float4*>(dst)[q] = o;
}

// W [K_,N] row-major -> B-fragment order (tf32).
// vec2 q -> lane l=q&31 (g,t), kb=(q>>5)%KB_, cb=(q>>5)/KB_:
//   {W[kb8+t][cb8+g], W[kb8+t+4][cb8+g]}
__global__ void prep_b_frag(const float* __restrict__ W, float* __restrict__ dst, int N) {
    int q = blockIdx.x * blockDim.x + threadIdx.x;
    if (q >= N * K_ / 2) return;
    int l = q & 31;
    int ck = q >> 5;
    int kb = ck % KB_, cb = ck / KB_;
    int g = l >> 2, t = l & 3;
    int n = cb * 8 + g, k0 = kb * 8 + t;
    float2 o;
    o.x = cvtf(W[(size_t)k0 * N + n]);
    o.y = cvtf(W[(size_t)(k0 + 4) * N + n]);
    reinterpret_cast<float2*>(dst)[q] = o;
}

// ---------------------------------------------------------------------------
// Fragment-order tf32 GEMM: C[4096,N] = A @ W + bias.
// BM=BN=128, BK=16; 256 thr = 8 warps (2x4); warp tile 64x32 (4x4 m16n8k8).
// A/B prepacked in fragment order: mainloop = LDS.128/LDS.64 + mma only.
// 3-stage cp.async pipeline; 2 CTAs/SM.
// ---------------------------------------------------------------------------
#define A_SLAB 2048                       // floats per stage (8 rb x 2 kb x 128)
#define B_SLAB 2048                       // floats per stage (16 cb x 2 kb x 64)
#define STAGE_FLOATS (A_SLAB + B_SLAB)
#define GSTG 3
#define GEMM_SMEM (GSTG * STAGE_FLOATS * 4)   // 48 KB

__global__ __launch_bounds__(256, 2) void gemm_frag_kernel(
        const float* __restrict__ A, const float* __restrict__ Bf,
        const float* __restrict__ bias, float* __restrict__ Cm,
        int N, int roundOut) {
    extern __shared__ float gsm[];

    const int tid  = threadIdx.x;
    const int lane = tid & 31;
    const int warp = tid >> 5;
    const int warpRow = warp >> 2;        // 0..1
    const int warpCol = warp & 3;         // 0..3
    const int g = lane >> 2, t = lane & 3;

    const int rb0 = blockIdx.y * 8;       // 8 row-blocks of 16
    const int cb0 = blockIdx.x * 16;      // 16 col-blocks of 8

    auto issue = [&](int s, int j) {      // j = k-iter, kb0 = 2j
        float* As = gsm + s * STAGE_FLOATS;
        float* Bs = As + A_SLAB;
        int kb0 = j * 2;
        #pragma unroll
        for (int i = 0; i < 2; i++) {
            int idx = tid + i * 256;                    // 0..511
            {   // A: 16 chunks (rb x kb) of 512B
                int chunk = idx >> 5, g16 = idx & 31;
                int rb = chunk >> 1, kb = chunk & 1;
                CP_ASYNC16(smem_u32(&As[((rb * 2 + kb) * 32 + g16) * 4]),
                           &A[(((size_t)(rb0 + rb) * KB_ + kb0 + kb) * 32 + g16) * 4]);
            }
            {   // B: 32 chunks (cb x kb) of 256B
                int chunk = idx >> 4, g16 = idx & 15;
                int cb = chunk >> 1, kb = chunk & 1;
                CP_ASYNC16(smem_u32(&Bs[((cb * 2 + kb) * 16 + g16) * 4]),
                           &Bf[(((size_t)(cb0 + cb) * KB_ + kb0 + kb) * 16 + g16) * 4]);
            }
        }
    };

    float acc[4][4][4];
    #pragma unroll
    for (int i = 0; i < 4; i++)
        #pragma unroll
        for (int j = 0; j < 4; j++)
            #pragma unroll
            for (int r = 0; r < 4; r++) acc[i][j][r] = 0.f;

    issue(0, 0); CP_COMMIT();
    issue(1, 1); CP_COMMIT();

    const int nIter = K_ / 16;            // 64
    for (int it = 0; it < nIter; it++) {
        CP_WAIT1();
        __syncthreads();
        if (it + 2 < nIter) issue((it + 2) % GSTG, it + 2);
        CP_COMMIT();

        const float* As = gsm + (it % GSTG) * STAGE_FLOATS;
        const float* Bs = As + A_SLAB;

        #pragma unroll
        for (int ks = 0; ks < 2; ks++) {
            unsigned a[4][4];
            #pragma unroll
            for (int mt = 0; mt < 4; mt++) {
                int rb = warpRow * 4 + mt;
                float4 av = *reinterpret_cast<const float4*>(
                    &As[((rb * 2 + ks) * 32 + lane) * 4]);
                a[mt][0] = __float_as_uint(av.x);
                a[mt][1] = __float_as_uint(av.y);
                a[mt][2] = __float_as_uint(av.z);
                a[mt][3] = __float_as_uint(av.w);
            }
            unsigned b[4][2];
            #pragma unroll
            for (int nt = 0; nt < 4; nt++) {
                int cb = warpCol * 4 + nt;
                float2 bv = *reinterpret_cast<const float2*>(
                    &Bs[(cb * 2 + ks) * 64 + g * 8 + t * 2]);
                b[nt][0] = __float_as_uint(bv.x);
                b[nt][1] = __float_as_uint(bv.y);
            }
            #pragma unroll
            for (int mt = 0; mt < 4; mt++)
                #pragma unroll
                for (int nt = 0; nt < 4; nt++) {
                    asm volatile(
                        "mma.sync.aligned.m16n8k8.row.col.f32.tf32.tf32.f32 "
                        "{%0,%1,%2,%3},{%4,%5,%6,%7},{%8,%9},{%0,%1,%2,%3};"
                        : "+f"(acc[mt][nt][0]), "+f"(acc[mt][nt][1]),
                          "+f"(acc[mt][nt][2]), "+f"(acc[mt][nt][3])
                        : "r"(a[mt][0]), "r"(a[mt][1]),
                          "r"(a[mt][2]), "r"(a[mt][3]),
                          "r"(b[nt][0]), "r"(b[nt][1]));
                }
        }
    }

    // Epilogue
    #pragma unroll
    for (int mt = 0; mt < 4; mt++) {
        int m0 = rb0 * 16 + warpRow * 64 + mt * 16 + g;
        #pragma unroll
        for (int nt = 0; nt < 4; nt++) {
            int n0 = cb0 * 8 + warpCol * 32 + nt * 8 + t * 2;
            float v0 = acc[mt][nt][0] + bias[n0];
            float v1 = acc[mt][nt][1] + bias[n0 + 1];
            float v2 = acc[mt][nt][2] + bias[n0];
            float v3 = acc[mt][nt][3] + bias[n0 + 1];
            if (roundOut) { v0 = cvtf(v0); v1 = cvtf(v1); v2 = cvtf(v2); v3 = cvtf(v3); }
            Cm[(size_t)m0 * N + n0    ] = v0;
            Cm[(size_t)m0 * N + n0 + 1] = v1;
            Cm[(size_t)(m0 + 8) * N + n0    ] = v2;
            Cm[(size_t)(m0 + 8) * N + n0 + 1] = v3;
        }
    }
}

// ---------------------------------------------------------------------------
// Tensor-core flash attention (causal, tf32 mma.sync). R3 geometry.
// qkv values are pre-rounded tf32 -> no cvt on Q/K/V loads.
// ---------------------------------------------------------------------------
#define AST 68
#define ATTN_SMEM_BYTES (4 * 64 * AST * 4)

__global__ __launch_bounds__(128) void attn_tc_kernel(
        const float* __restrict__ qkv,
        float* __restrict__ out) {
    int qt = blockIdx.x;
    int h  = blockIdx.y;
    int b  = blockIdx.z;

    extern __shared__ unsigned smu[];
    unsigned* Qs = smu;
    unsigned* Ks = Qs + 64 * AST;
    unsigned* Vs = Ks + 64 * AST;
    unsigned* Ps = Vs + 64 * AST;

    const int tid  = threadIdx.x;
    const int lane = tid & 31;
    const int warp = tid >> 5;
    const int g = lane >> 2;
    const int t = lane & 3;
    const int m0 = warp * 16;

    const float scale = 0.125f;   // exact power of 2: tf32-safe
    const float* base = qkv + (size_t)b * T_ * QKV_N;
    const int q0 = qt * 64;
    const int hoff = h * D_;

    for (int i = tid; i < 64 * 16; i += 128) {
        int r = i >> 4, q = i & 15;
        float4 v = *reinterpret_cast<const float4*>(
            &base[(size_t)(q0 + r) * QKV_N + hoff + q * 4]);
        unsigned* dst = &Qs[r * AST + q * 4];
        dst[0] = __float_as_uint(v.x * scale);
        dst[1] = __float_as_uint(v.y * scale);
        dst[2] = __float_as_uint(v.z * scale);
        dst[3] = __float_as_uint(v.w * scale);
    }

    float o[8][4];
    #pragma unroll
    for (int d = 0; d < 8; d++)
        #pragma unroll
        for (int r = 0; r < 4; r++) o[d][r] = 0.f;
    float mRow[2] = {-INFINITY, -INFINITY};
    float lRow[2] = {0.f, 0.f};

    __syncthreads();

    for (int kt = 0; kt <= qt; kt++) {
        int k0 = kt * 64;
        for (int i = tid; i < 64 * 16; i += 128) {
            int r = i >> 4, q = i & 15;
            size_t rowbase = (size_t)(k0 + r) * QKV_N + hoff + q * 4;
            float4 kv = *reinterpret_cast<const float4*>(&base[rowbase + C_]);
            float4 vv = *reinterpret_cast<const float4*>(&base[rowbase + 2 * C_]);
            unsigned* dk = &Ks[r * AST + q * 4];
            dk[0] = __float_as_uint(kv.x); dk[1] = __float_as_uint(kv.y);
            dk[2] = __float_as_uint(kv.z); dk[3] = __float_as_uint(kv.w);
            unsigned* dv = &Vs[r * AST + q * 4];
            dv[0] = __float_as_uint(vv.x); dv[1] = __float_as_uint(vv.y);
            dv[2] = __float_as_uint(vv.z); dv[3] = __float_as_uint(vv.w);
        }
        __syncthreads();

        float s[8][4];
        #pragma unroll
        for (int n = 0; n < 8; n++)
            #pragma unroll
            for (int r = 0; r < 4; r++) s[n][r] = 0.f;

        #pragma unroll
        for (int kk = 0; kk < 8; kk++) {
            unsigned a0 = Qs[(m0 + g    ) * AST + kk * 8 + t    ];
            unsigned a1 = Qs[(m0 + g + 8) * AST + kk * 8 + t    ];
            unsigned a2 = Qs[(m0 + g    ) * AST + kk * 8 + t + 4];
            unsigned a3 = Qs[(m0 + g + 8) * AST + kk * 8 + t + 4];
            #pragma unroll
            for (int n = 0; n < 8; n++) {
                unsigned b0 = Ks[(n * 8 + g) * AST + kk * 8 + t    ];
                unsigned b1 = Ks[(n * 8 + g) * AST + kk * 8 + t + 4];
                asm volatile(
                    "mma.sync.aligned.m16n8k8.row.col.f32.tf32.tf32.f32 "
                    "{%0,%1,%2,%3},{%4,%5,%6,%7},{%8,%9},{%0,%1,%2,%3};"
                    : "+f"(s[n][0]), "+f"(s[n][1]),
                      "+f"(s[n][2]), "+f"(s[n][3])
                    : "r"(a0), "r"(a1), "r"(a2), "r"(a3), "r"(b0), "r"(b1));
            }
        }

        if (kt == qt) {
            #pragma unroll
            for (int n = 0; n < 8; n++) {
                int c0 = n * 8 + 2 * t;
                int r0 = m0 + g, r1 = m0 + g + 8;
                if (c0     > r0) s[n][0] = -INFINITY;
                if (c0 + 1 > r0) s[n][1] = -INFINITY;
                if (c0     > r1) s[n][2] = -INFINITY;
                if (c0 + 1 > r1) s[n][3] = -INFINITY;
            }
        }

        #pragma unroll
        for (int half = 0; half < 2; half++) {
            float pm = -INFINITY;
            #pragma unroll
            for (int n = 0; n < 8; n++) {
                pm = fmaxf(pm, s[n][2 * half]);
                pm = fmaxf(pm, s[n][2 * half + 1]);
            }
            pm = fmaxf(pm, __shfl_xor_sync(0xffffffff, pm, 1));
            pm = fmaxf(pm, __shfl_xor_sync(0xffffffff, pm, 2));

            float mNew = fmaxf(mRow[half], pm);
            float alpha = __expf(mRow[half] - mNew);
            float lsum = 0.f;
            #pragma unroll
            for (int n = 0; n < 8; n++) {
                float p0 = __expf(s[n][2 * half    ] - mNew);
                float p1 = __expf(s[n][2 * half + 1] - mNew);
                s[n][2 * half    ] = p0;
                s[n][2 * half + 1] = p1;
                lsum += p0 + p1;
            }
            lsum += __shfl_xor_sync(0xffffffff, lsum, 1);
            lsum += __shfl_xor_sync(0xffffffff, lsum, 2);
            mRow[half] = mNew;
            lRow[half] = lRow[half] * alpha + lsum;
            #pragma unroll
            for (int n = 0; n < 8; n++) {
                o[n][2 * half    ] *= alpha;
                o[n][2 * half + 1] *= alpha;
            }
        }

        #pragma unroll
        for (int n = 0; n < 8; n++) {
            int c = n * 8 + 2 * t;
            Ps[(m0 + g    ) * AST + c    ] = f2tf32(s[n][0]);
            Ps[(m0 + g    ) * AST + c + 1] = f2tf32(s[n][1]);
            Ps[(m0 + g + 8) * AST + c    ] = f2tf32(s[n][2]);
            Ps[(m0 + g + 8) * AST + c + 1] = f2tf32(s[n][3]);
        }
        __syncwarp();

        #pragma unroll
        for (int kk = 0; kk < 8; kk++) {
            unsigned a0 = Ps[(m0 + g    ) * AST + kk * 8 + t    ];
            unsigned a1 = Ps[(m0 + g + 8) * AST + kk * 8 + t    ];
            unsigned a2 = Ps[(m0 + g    ) * AST + kk * 8 + t + 4];
            unsigned a3 = Ps[(m0 + g + 8) * AST + kk * 8 + t + 4];
            #pragma unroll
            for (int d = 0; d < 8; d++) {
                unsigned b0 = Vs[(kk * 8 + t    ) * AST + d * 8 + g];
                unsigned b1 = Vs[(kk * 8 + t + 4) * AST + d * 8 + g];
                asm volatile(
                    "mma.sync.aligned.m16n8k8.row.col.f32.tf32.tf32.f32 "
                    "{%0,%1,%2,%3},{%4,%5,%6,%7},{%8,%9},{%0,%1,%2,%3};"
                    : "+f"(o[d][0]), "+f"(o[d][1]),
                      "+f"(o[d][2]), "+f"(o[d][3])
                    : "r"(a0), "r"(a1), "r"(a2), "r"(a3), "r"(b0), "r"(b1));
            }
        }
        __syncthreads();
    }

    #pragma unroll
    for (int half = 0; half < 2; half++) {
        float inv = 1.0f / lRow[half];
        int row = q0 + m0 + g + half * 8;
        #pragma unroll
        for (int d = 0; d < 8; d++) {
            int col = hoff + d * 8 + 2 * t;
            out[((size_t)b * T_ + row) * C_ + col    ] = o[d][2 * half    ] * inv;
            out[((size_t)b * T_ + row) * C_ + col + 1] = o[d][2 * half + 1] * inv;
        }
    }
}

// ---------------------------------------------------------------------------
extern "C" void kernel_launch(void* const* d_in, const int* in_sizes, int n_in,
                              void* d_out, int out_size) {
    const float* x     = (const float*)d_in[0];
    const float* Wqkv  = (const float*)d_in[1];
    const float* bqkv  = (const float*)d_in[2];
    const float* Wproj = (const float*)d_in[3];
    const float* bproj = (const float*)d_in[4];
    float* out = (float*)d_out;

    float *qkv, *attn, *af, *wqkvF, *wprojF;
    cudaGetSymbolAddress((void**)&qkv,    g_qkv);
    cudaGetSymbolAddress((void**)&attn,   g_attn);
    cudaGetSymbolAddress((void**)&af,     g_af);
    cudaGetSymbolAddress((void**)&wqkvF,  g_wqkvF);
    cudaGetSymbolAddress((void**)&wprojF, g_wprojF);

    cudaFuncSetAttribute(gemm_frag_kernel,
                         cudaFuncAttributeMaxDynamicSharedMemorySize, GEMM_SMEM);
    cudaFuncSetAttribute(attn_tc_kernel,
                         cudaFuncAttributeMaxDynamicSharedMemorySize, ATTN_SMEM_BYTES);

    // 0) prep: tf32 convert + fragment packing
    prep_a_frag<<<(M_ * K_ / 4) / 256, 256>>>(x, af);
    prep_b_frag<<<(QKV_N * K_ / 2) / 256, 256>>>(Wqkv, wqkvF, QKV_N);
    prep_b_frag<<<(C_ * K_ / 2) / 256, 256>>>(Wproj, wprojF, C_);

    // 1) QKV projection (output tf32-rounded for cvt-free attention)
    {
        dim3 grid(QKV_N / 128, M_ / 128);
        gemm_frag_kernel<<<grid, 256, GEMM_SMEM>>>(af, wqkvF, bqkv, qkv, QKV_N, 1);
    }
    // 2) Causal flash attention
    {
        dim3 grid(T_ / 64, H_, B_);
        attn_tc_kernel<<<grid, 128, ATTN_SMEM_BYTES>>>(qkv, attn);
    }
    // 3) repack O into fragment order, then output projection (full fp32 out)
    prep_a_frag<<<(M_ * K_ / 4) / 256, 256>>>(attn, af);
    {
        dim3 grid(C_ / 128, M_ / 128);
        gemm_frag_kernel<<<grid, 256, GEMM_SMEM>>>(af, wprojF, bproj, out, C_, 0);
    }
}

// round 14
// speedup vs baseline: 1.3870x; 1.1564x over previous
#include <cuda_runtime.h>
#include <math.h>

// Problem constants
#define B_  2
#define T_  2048
#define C_  1024
#define H_  16
#define D_  64
#define M_  4096             // B*T
#define QKV_N 3072
#define K_  1024
#define KB_ (K_ / 8)         // 128 k-blocks of 8

// Scratch (allocation-free rule: __device__ globals)
__device__ float g_qkv[(size_t)M_ * QKV_N];    // QKV out (tf32-rounded, row-major)
__device__ float g_attn[(size_t)M_ * C_];      // attention O (fp32, row-major)
__device__ float g_af[(size_t)M_ * C_];        // A-fragments (x, then O)
__device__ float g_wqkvF[(size_t)K_ * QKV_N];  // B-fragments of W_qkv
__device__ float g_wprojF[(size_t)K_ * C_];    // B-fragments of W_proj
__device__ float g_Qf[(size_t)M_ * C_];        // Q fragments (scaled)
__device__ float g_Kf[(size_t)M_ * C_];        // K fragments
__device__ float g_Vf[(size_t)M_ * C_];        // V fragments

// ---------------------------------------------------------------------------
__device__ __forceinline__ unsigned f2tf32(float f) {
    unsigned u;
    asm("cvt.rna.tf32.f32 %0, %1;" : "=r"(u) : "f"(f));
    return u;
}
__device__ __forceinline__ float cvtf(float v) {
    return __uint_as_float(f2tf32(v));
}
__device__ __forceinline__ unsigned smem_u32(const void* p) {
    return (unsigned)__cvta_generic_to_shared(p);
}
#define CP_ASYNC16(dst, src) \
    asm volatile("cp.async.cg.shared.global [%0], [%1], 16;" \
                 :: "r"(dst), "l"(src))
#define CP_COMMIT()  asm volatile("cp.async.commit_group;")
#define CP_WAIT1()   asm volatile("cp.async.wait_group 1;")

#define MMA_TF32(acc, a0, a1, a2, a3, b0, b1) \
    asm volatile( \
        "mma.sync.aligned.m16n8k8.row.col.f32.tf32.tf32.f32 " \
        "{%0,%1,%2,%3},{%4,%5,%6,%7},{%8,%9},{%0,%1,%2,%3};" \
        : "+f"((acc)[0]), "+f"((acc)[1]), "+f"((acc)[2]), "+f"((acc)[3]) \
        : "r"(a0), "r"(a1), "r"(a2), "r"(a3), "r"(b0), "r"(b1))

// ---------------------------------------------------------------------------
// GEMM prep: row-major -> fragment order (tf32). (unchanged from R13)
// ---------------------------------------------------------------------------
__global__ void prep_a_frag(const float* __restrict__ src, float* __restrict__ dst) {
    int q = blockIdx.x * blockDim.x + threadIdx.x;
    if (q >= M_ * K_ / 4) return;
    int l = q & 31;
    int rk = q >> 5;
    int kb = rk % KB_, rb = rk / KB_;
    int g = l >> 2, t = l & 3;
    int r0 = rb * 16 + g, c0 = kb * 8 + t;
    float4 o;
    o.x = cvtf(src[(size_t)r0 * K_ + c0]);
    o.y = cvtf(src[(size_t)(r0 + 8) * K_ + c0]);
    o.z = cvtf(src[(size_t)r0 * K_ + c0 + 4]);
    o.w = cvtf(src[(size_t)(r0 + 8) * K_ + c0 + 4]);
    reinterpret_cast<float4*>(dst)[q] = o;
}

__global__ void prep_b_frag(const float* __restrict__ W, float* __restrict__ dst, int N) {
    int q = blockIdx.x * blockDim.x + threadIdx.x;
    if (q >= N * K_ / 2) return;
    int l = q & 31;
    int ck = q >> 5;
    int kb = ck % KB_, cb = ck / KB_;
    int g = l >> 2, t = l & 3;
    int n = cb * 8 + g, k0 = kb * 8 + t;
    float2 o;
    o.x = cvtf(W[(size_t)k0 * N + n]);
    o.y = cvtf(W[(size_t)(k0 + 4) * N + n]);
    reinterpret_cast<float2*>(dst)[q] = o;
}

// ---------------------------------------------------------------------------
// Attention prep: qkv (tf32-rounded) -> per-(b,h) fragment arrays.
// Qf: [bh][tb(128)][kk(8)][lane(32)] float4  (A-frags, scale folded)
// Kf: [bh][kt(32)][n(8)][kk(8)][lane] float2 (B-frags of K)
// Vf: [bh][kt(32)][d(8)][kk(8)][lane] float2 (B-frags of V)
// ---------------------------------------------------------------------------
__global__ void prep_qf(const float* __restrict__ qkv, float* __restrict__ Qf) {
    int gid = blockIdx.x * blockDim.x + threadIdx.x;    // 1,048,576
    if (gid >= 32 * 128 * 8 * 32) return;
    int lane = gid & 31, kk = (gid >> 5) & 7, tb = (gid >> 8) & 127, bh = gid >> 15;
    int g = lane >> 2, t = lane & 3;
    int b = bh >> 4, h = bh & 15;
    size_t base = (size_t)(b * T_ + tb * 16 + g) * QKV_N + h * 64;
    int c = kk * 8 + t;
    float4 o;
    o.x = qkv[base + c] * 0.125f;
    o.y = qkv[base + (size_t)8 * QKV_N + c] * 0.125f;
    o.z = qkv[base + c + 4] * 0.125f;
    o.w = qkv[base + (size_t)8 * QKV_N + c + 4] * 0.125f;
    reinterpret_cast<float4*>(Qf)[gid] = o;
}

__global__ void prep_kf(const float* __restrict__ qkv, float* __restrict__ Kf) {
    int gid = blockIdx.x * blockDim.x + threadIdx.x;    // 2,097,152
    if (gid >= 32 * 32 * 8 * 8 * 32) return;
    int lane = gid & 31, kk = (gid >> 5) & 7, n = (gid >> 8) & 7;
    int kt = (gid >> 11) & 31, bh = gid >> 16;
    int g = lane >> 2, t = lane & 3;
    int b = bh >> 4, h = bh & 15;
    int token = kt * 64 + n * 8 + g;
    size_t base = (size_t)(b * T_ + token) * QKV_N + C_ + h * 64;
    int c = kk * 8 + t;
    float2 o = { qkv[base + c], qkv[base + c + 4] };
    reinterpret_cast<float2*>(Kf)[gid] = o;
}

__global__ void prep_vf(const float* __restrict__ qkv, float* __restrict__ Vf) {
    int gid = blockIdx.x * blockDim.x + threadIdx.x;    // 2,097,152
    if (gid >= 32 * 32 * 8 * 8 * 32) return;
    int lane = gid & 31, kk = (gid >> 5) & 7, d = (gid >> 8) & 7;
    int kt = (gid >> 11) & 31, bh = gid >> 16;
    int g = lane >> 2, t = lane & 3;
    int b = bh >> 4, h = bh & 15;
    int token = kt * 64 + kk * 8 + t;
    size_t base = (size_t)(b * T_ + token) * QKV_N + 2 * C_ + h * 64;
    int c = d * 8 + g;
    float2 o = { qkv[base + c], qkv[base + (size_t)4 * QKV_N + c] };
    reinterpret_cast<float2*>(Vf)[gid] = o;
}

// ---------------------------------------------------------------------------
// Fragment-order tf32 GEMM (unchanged from R13).
// ---------------------------------------------------------------------------
#define A_SLAB 2048
#define B_SLAB 2048
#define STAGE_FLOATS (A_SLAB + B_SLAB)
#define GSTG 3
#define GEMM_SMEM (GSTG * STAGE_FLOATS * 4)

__global__ __launch_bounds__(256, 2) void gemm_frag_kernel(
        const float* __restrict__ A, const float* __restrict__ Bf,
        const float* __restrict__ bias, float* __restrict__ Cm,
        int N, int roundOut) {
    extern __shared__ float gsm[];

    const int tid  = threadIdx.x;
    const int lane = tid & 31;
    const int warp = tid >> 5;
    const int warpRow = warp >> 2;
    const int warpCol = warp & 3;
    const int g = lane >> 2, t = lane & 3;

    const int rb0 = blockIdx.y * 8;
    const int cb0 = blockIdx.x * 16;

    auto issue = [&](int s, int j) {
        float* As = gsm + s * STAGE_FLOATS;
        float* Bs = As + A_SLAB;
        int kb0 = j * 2;
        #pragma unroll
        for (int i = 0; i < 2; i++) {
            int idx = tid + i * 256;
            {
                int chunk = idx >> 5, g16 = idx & 31;
                int rb = chunk >> 1, kb = chunk & 1;
                CP_ASYNC16(smem_u32(&As[((rb * 2 + kb) * 32 + g16) * 4]),
                           &A[(((size_t)(rb0 + rb) * KB_ + kb0 + kb) * 32 + g16) * 4]);
            }
            {
                int chunk = idx >> 4, g16 = idx & 15;
                int cb = chunk >> 1, kb = chunk & 1;
                CP_ASYNC16(smem_u32(&Bs[((cb * 2 + kb) * 16 + g16) * 4]),
                           &Bf[(((size_t)(cb0 + cb) * KB_ + kb0 + kb) * 16 + g16) * 4]);
            }
        }
    };

    float acc[4][4][4];
    #pragma unroll
    for (int i = 0; i < 4; i++)
        #pragma unroll
        for (int j = 0; j < 4; j++)
            #pragma unroll
            for (int r = 0; r < 4; r++) acc[i][j][r] = 0.f;

    issue(0, 0); CP_COMMIT();
    issue(1, 1); CP_COMMIT();

    const int nIter = K_ / 16;
    for (int it = 0; it < nIter; it++) {
        CP_WAIT1();
        __syncthreads();
        if (it + 2 < nIter) issue((it + 2) % GSTG, it + 2);
        CP_COMMIT();

        const float* As = gsm + (it % GSTG) * STAGE_FLOATS;
        const float* Bs = As + A_SLAB;

        #pragma unroll
        for (int ks = 0; ks < 2; ks++) {
            unsigned a[4][4];
            #pragma unroll
            for (int mt = 0; mt < 4; mt++) {
                int rb = warpRow * 4 + mt;
                float4 av = *reinterpret_cast<const float4*>(
                    &As[((rb * 2 + ks) * 32 + lane) * 4]);
                a[mt][0] = __float_as_uint(av.x);
                a[mt][1] = __float_as_uint(av.y);
                a[mt][2] = __float_as_uint(av.z);
                a[mt][3] = __float_as_uint(av.w);
            }
            unsigned b[4][2];
            #pragma unroll
            for (int nt = 0; nt < 4; nt++) {
                int cb = warpCol * 4 + nt;
                float2 bv = *reinterpret_cast<const float2*>(
                    &Bs[(cb * 2 + ks) * 64 + g * 8 + t * 2]);
                b[nt][0] = __float_as_uint(bv.x);
                b[nt][1] = __float_as_uint(bv.y);
            }
            #pragma unroll
            for (int mt = 0; mt < 4; mt++)
                #pragma unroll
                for (int nt = 0; nt < 4; nt++)
                    MMA_TF32(acc[mt][nt], a[mt][0], a[mt][1], a[mt][2], a[mt][3],
                             b[nt][0], b[nt][1]);
        }
    }

    #pragma unroll
    for (int mt = 0; mt < 4; mt++) {
        int m0 = rb0 * 16 + warpRow * 64 + mt * 16 + g;
        #pragma unroll
        for (int nt = 0; nt < 4; nt++) {
            int n0 = cb0 * 8 + warpCol * 32 + nt * 8 + t * 2;
            float v0 = acc[mt][nt][0] + bias[n0];
            float v1 = acc[mt][nt][1] + bias[n0 + 1];
            float v2 = acc[mt][nt][2] + bias[n0];
            float v3 = acc[mt][nt][3] + bias[n0 + 1];
            if (roundOut) { v0 = cvtf(v0); v1 = cvtf(v1); v2 = cvtf(v2); v3 = cvtf(v3); }
            Cm[(size_t)m0 * N + n0    ] = v0;
            Cm[(size_t)m0 * N + n0 + 1] = v1;
            Cm[(size_t)(m0 + 8) * N + n0    ] = v2;
            Cm[(size_t)(m0 + 8) * N + n0 + 1] = v3;
        }
    }
}

// ---------------------------------------------------------------------------
// Attention v2: fragment-order Q/K/V, Q in registers, cp.async double buffer.
// Block = (128-row q-tile, head, batch); 256 thr = 8 warps x 16 Q-rows.
// ---------------------------------------------------------------------------
#define ATT_STAGE 8192                       // floats: Kf tile 4096 + Vf tile 4096
#define ATT_PS (16 * 68)                     // per-warp P buffer (floats)
#define ATT_SMEM ((2 * ATT_STAGE + 8 * ATT_PS) * 4)   // 100,352 bytes

__global__ __launch_bounds__(256, 2) void attn_v2_kernel(
        const float* __restrict__ Qf, const float* __restrict__ Kf,
        const float* __restrict__ Vf, float* __restrict__ out) {
    int qt = blockIdx.x;                      // 0..15
    int h  = blockIdx.y;
    int b  = blockIdx.z;
    int bh = b * H_ + h;

    extern __shared__ float asm_[];

    const int tid  = threadIdx.x;
    const int lane = tid & 31;
    const int warp = tid >> 5;                // 0..7
    const int g = lane >> 2, t = lane & 3;
    const int m0 = warp * 16;
    const int q0 = qt * 128;

    // Q fragments -> registers (once per block)
    unsigned q[8][4];
    {
        const float4* qsrc = reinterpret_cast<const float4*>(Qf)
                           + ((size_t)bh * 128 + qt * 8 + warp) * 256;
        #pragma unroll
        for (int kk = 0; kk < 8; kk++) {
            float4 v = qsrc[kk * 32 + lane];
            q[kk][0] = __float_as_uint(v.x);
            q[kk][1] = __float_as_uint(v.y);
            q[kk][2] = __float_as_uint(v.z);
            q[kk][3] = __float_as_uint(v.w);
        }
    }

    float o[8][4];
    #pragma unroll
    for (int d = 0; d < 8; d++)
        #pragma unroll
        for (int r = 0; r < 4; r++) o[d][r] = 0.f;
    float mRow[2] = {-INFINITY, -INFINITY};
    float lRow[2] = {0.f, 0.f};

    auto issue = [&](int s, int kt) {
        const float4* ks = reinterpret_cast<const float4*>(Kf)
                         + ((size_t)bh * 32 + kt) * 1024;
        const float4* vs = reinterpret_cast<const float4*>(Vf)
                         + ((size_t)bh * 32 + kt) * 1024;
        unsigned dK = smem_u32(asm_ + s * ATT_STAGE);
        unsigned dV = dK + 4096 * 4;
        #pragma unroll
        for (int i = 0; i < 4; i++) {
            int idx = tid + i * 256;          // 0..1023
            CP_ASYNC16(dK + idx * 16, ks + idx);
            CP_ASYNC16(dV + idx * 16, vs + idx);
        }
    };

    const int ktMax = 2 * qt + 1;
    issue(0, 0); CP_COMMIT();

    for (int kt = 0; kt <= ktMax; kt++) {
        if (kt < ktMax) issue((kt + 1) & 1, kt + 1);
        CP_COMMIT();
        CP_WAIT1();
        __syncthreads();

        int k0 = kt * 64;
        if (k0 <= q0 + m0 + 15) {             // causal warp skip
            const float* Ksm = asm_ + (kt & 1) * ATT_STAGE;
            const float* Vsm = Ksm + 4096;
            float* Psw = asm_ + 2 * ATT_STAGE + warp * ATT_PS;

            // ---- S = Q @ K^T ----
            float s[8][4];
            #pragma unroll
            for (int n = 0; n < 8; n++)
                #pragma unroll
                for (int r = 0; r < 4; r++) s[n][r] = 0.f;

            #pragma unroll
            for (int kk = 0; kk < 8; kk++) {
                #pragma unroll
                for (int n = 0; n < 8; n++) {
                    float2 bv = *reinterpret_cast<const float2*>(
                        &Ksm[((n * 8 + kk) * 32 + lane) * 2]);
                    MMA_TF32(s[n], q[kk][0], q[kk][1], q[kk][2], q[kk][3],
                             __float_as_uint(bv.x), __float_as_uint(bv.y));
                }
            }

            // ---- causal mask where tile crosses diagonal ----
            if (k0 + 63 > q0 + m0) {
                int r0 = q0 + m0 + g, r1 = r0 + 8;
                #pragma unroll
                for (int n = 0; n < 8; n++) {
                    int c0 = k0 + n * 8 + 2 * t;
                    if (c0     > r0) s[n][0] = -INFINITY;
                    if (c0 + 1 > r0) s[n][1] = -INFINITY;
                    if (c0     > r1) s[n][2] = -INFINITY;
                    if (c0 + 1 > r1) s[n][3] = -INFINITY;
                }
            }

            // ---- online softmax ----
            #pragma unroll
            for (int half = 0; half < 2; half++) {
                float pm = -INFINITY;
                #pragma unroll
                for (int n = 0; n < 8; n++) {
                    pm = fmaxf(pm, s[n][2 * half]);
                    pm = fmaxf(pm, s[n][2 * half + 1]);
                }
                pm = fmaxf(pm, __shfl_xor_sync(0xffffffff, pm, 1));
                pm = fmaxf(pm, __shfl_xor_sync(0xffffffff, pm, 2));

                float mNew = fmaxf(mRow[half], pm);
                float alpha = __expf(mRow[half] - mNew);
                float lsum = 0.f;
                #pragma unroll
                for (int n = 0; n < 8; n++) {
                    float p0 = __expf(s[n][2 * half    ] - mNew);
                    float p1 = __expf(s[n][2 * half + 1] - mNew);
                    s[n][2 * half    ] = p0;
                    s[n][2 * half + 1] = p1;
                    lsum += p0 + p1;
                }
                lsum += __shfl_xor_sync(0xffffffff, lsum, 1);
                lsum += __shfl_xor_sync(0xffffffff, lsum, 2);
                mRow[half] = mNew;
                lRow[half] = lRow[half] * alpha + lsum;
                #pragma unroll
                for (int n = 0; n < 8; n++) {
                    o[n][2 * half    ] *= alpha;
                    o[n][2 * half + 1] *= alpha;
                }
            }

            // ---- P (tf32) -> warp-private smem ----
            #pragma unroll
            for (int n = 0; n < 8; n++) {
                int c = n * 8 + 2 * t;
                float2 lo = { __uint_as_float(f2tf32(s[n][0])),
                              __uint_as_float(f2tf32(s[n][1])) };
                float2 hi = { __uint_as_float(f2tf32(s[n][2])),
                              __uint_as_float(f2tf32(s[n][3])) };
                *reinterpret_cast<float2*>(&Psw[g * 68 + c])       = lo;
                *reinterpret_cast<float2*>(&Psw[(g + 8) * 68 + c]) = hi;
            }
            __syncwarp();

            // ---- O += P @ V ----
            #pragma unroll
            for (int kk = 0; kk < 8; kk++) {
                unsigned a0 = __float_as_uint(Psw[g * 68       + kk * 8 + t    ]);
                unsigned a1 = __float_as_uint(Psw[(g + 8) * 68 + kk * 8 + t    ]);
                unsigned a2 = __float_as_uint(Psw[g * 68       + kk * 8 + t + 4]);
                unsigned a3 = __float_as_uint(Psw[(g + 8) * 68 + kk * 8 + t + 4]);
                #pragma unroll
                for (int d = 0; d < 8; d++) {
                    float2 bv = *reinterpret_cast<const float2*>(
                        &Vsm[((d * 8 + kk) * 32 + lane) * 2]);
                    MMA_TF32(o[d], a0, a1, a2, a3,
                             __float_as_uint(bv.x), __float_as_uint(bv.y));
                }
            }
        }
        __syncthreads();
    }

    // ---- epilogue ----
    #pragma unroll
    for (int half = 0; half < 2; half++) {
        float inv = 1.0f / lRow[half];
        int row = q0 + m0 + g + half * 8;
        #pragma unroll
        for (int d = 0; d < 8; d++) {
            int col = h * D_ + d * 8 + 2 * t;
            out[((size_t)b * T_ + row) * C_ + col    ] = o[d][2 * half    ] * inv;
            out[((size_t)b * T_ + row) * C_ + col + 1] = o[d][2 * half + 1] * inv;
        }
    }
}

// ---------------------------------------------------------------------------
extern "C" void kernel_launch(void* const* d_in, const int* in_sizes, int n_in,
                              void* d_out, int out_size) {
    const float* x     = (const float*)d_in[0];
    const float* Wqkv  = (const float*)d_in[1];
    const float* bqkv  = (const float*)d_in[2];
    const float* Wproj = (const float*)d_in[3];
    const float* bproj = (const float*)d_in[4];
    float* out = (float*)d_out;

    float *qkv, *attn, *af, *wqkvF, *wprojF, *Qf, *Kf, *Vf;
    cudaGetSymbolAddress((void**)&qkv,    g_qkv);
    cudaGetSymbolAddress((void**)&attn,   g_attn);
    cudaGetSymbolAddress((void**)&af,     g_af);
    cudaGetSymbolAddress((void**)&wqkvF,  g_wqkvF);
    cudaGetSymbolAddress((void**)&wprojF, g_wprojF);
    cudaGetSymbolAddress((void**)&Qf,     g_Qf);
    cudaGetSymbolAddress((void**)&Kf,     g_Kf);
    cudaGetSymbolAddress((void**)&Vf,     g_Vf);

    cudaFuncSetAttribute(gemm_frag_kernel,
                         cudaFuncAttributeMaxDynamicSharedMemorySize, GEMM_SMEM);
    cudaFuncSetAttribute(attn_v2_kernel,
                         cudaFuncAttributeMaxDynamicSharedMemorySize, ATT_SMEM);

    // 0) GEMM input prep
    prep_a_frag<<<(M_ * K_ / 4) / 256, 256>>>(x, af);
    prep_b_frag<<<(QKV_N * K_ / 2) / 256, 256>>>(Wqkv, wqkvF, QKV_N);
    prep_b_frag<<<(C_ * K_ / 2) / 256, 256>>>(Wproj, wprojF, C_);

    // 1) QKV projection (tf32-rounded output)
    {
        dim3 grid(QKV_N / 128, M_ / 128);
        gemm_frag_kernel<<<grid, 256, GEMM_SMEM>>>(af, wqkvF, bqkv, qkv, QKV_N, 1);
    }

    // 2) attention prep: Q/K/V fragment arrays
    prep_qf<<<(32 * 128 * 8 * 32) / 256, 256>>>(qkv, Qf);
    prep_kf<<<(32 * 32 * 8 * 8 * 32) / 256, 256>>>(qkv, Kf);
    prep_vf<<<(32 * 32 * 8 * 8 * 32) / 256, 256>>>(qkv, Vf);

    // 3) causal flash attention (fragment-order, double-buffered)
    {
        dim3 grid(T_ / 128, H_, B_);
        attn_v2_kernel<<<grid, 256, ATT_SMEM>>>(Qf, Kf, Vf, attn);
    }

    // 4) repack O, output projection
    prep_a_frag<<<(M_ * K_ / 4) / 256, 256>>>(attn, af);
    {
        dim3 grid(C_ / 128, M_ / 128);
        gemm_frag_kernel<<<grid, 256, GEMM_SMEM>>>(af, wprojF, bproj, out, C_, 0);
    }
}

// round 15
// speedup vs baseline: 1.4759x; 1.0641x over previous
#include <cuda_runtime.h>
#include <math.h>

// Problem constants
#define B_  2
#define T_  2048
#define C_  1024
#define H_  16
#define D_  64
#define M_  4096             // B*T
#define QKV_N 3072
#define K_  1024
#define KB_ (K_ / 8)         // 128 k-blocks of 8

// Scratch (allocation-free rule: __device__ globals)
__device__ float g_qkv[(size_t)M_ * QKV_N];    // QKV out (tf32-rounded, row-major)
__device__ float g_af[(size_t)M_ * C_];        // A-fragments (x, then O)
__device__ float g_wqkvF[(size_t)K_ * QKV_N];  // B-fragments of W_qkv
__device__ float g_wprojF[(size_t)K_ * C_];    // B-fragments of W_proj
__device__ float g_Qf[(size_t)M_ * C_];        // Q fragments (scaled)
__device__ float g_Kf[(size_t)M_ * C_];        // K fragments
__device__ float g_Vf[(size_t)M_ * C_];        // V fragments

// ---------------------------------------------------------------------------
__device__ __forceinline__ unsigned f2tf32(float f) {
    unsigned u;
    asm("cvt.rna.tf32.f32 %0, %1;" : "=r"(u) : "f"(f));
    return u;
}
__device__ __forceinline__ float cvtf(float v) {
    return __uint_as_float(f2tf32(v));
}
__device__ __forceinline__ unsigned smem_u32(const void* p) {
    return (unsigned)__cvta_generic_to_shared(p);
}
#define CP_ASYNC16(dst, src) \
    asm volatile("cp.async.cg.shared.global [%0], [%1], 16;" \
                 :: "r"(dst), "l"(src))
#define CP_COMMIT()  asm volatile("cp.async.commit_group;")
#define CP_WAIT1()   asm volatile("cp.async.wait_group 1;")

#define MMA_TF32(acc, a0, a1, a2, a3, b0, b1) \
    asm volatile( \
        "mma.sync.aligned.m16n8k8.row.col.f32.tf32.tf32.f32 " \
        "{%0,%1,%2,%3},{%4,%5,%6,%7},{%8,%9},{%0,%1,%2,%3};" \
        : "+f"((acc)[0]), "+f"((acc)[1]), "+f"((acc)[2]), "+f"((acc)[3]) \
        : "r"(a0), "r"(a1), "r"(a2), "r"(a3), "r"(b0), "r"(b1))

// ---------------------------------------------------------------------------
// GEMM prep: row-major -> fragment order (tf32).
// ---------------------------------------------------------------------------
__global__ void prep_a_frag(const float* __restrict__ src, float* __restrict__ dst) {
    int q = blockIdx.x * blockDim.x + threadIdx.x;
    if (q >= M_ * K_ / 4) return;
    int l = q & 31;
    int rk = q >> 5;
    int kb = rk % KB_, rb = rk / KB_;
    int g = l >> 2, t = l & 3;
    int r0 = rb * 16 + g, c0 = kb * 8 + t;
    float4 o;
    o.x = cvtf(src[(size_t)r0 * K_ + c0]);
    o.y = cvtf(src[(size_t)(r0 + 8) * K_ + c0]);
    o.z = cvtf(src[(size_t)r0 * K_ + c0 + 4]);
    o.w = cvtf(src[(size_t)(r0 + 8) * K_ + c0 + 4]);
    reinterpret_cast<float4*>(dst)[q] = o;
}

__global__ void prep_b_frag(const float* __restrict__ W, float* __restrict__ dst, int N) {
    int q = blockIdx.x * blockDim.x + threadIdx.x;
    if (q >= N * K_ / 2) return;
    int l = q & 31;
    int ck = q >> 5;
    int kb = ck % KB_, cb = ck / KB_;
    int g = l >> 2, t = l & 3;
    int n = cb * 8 + g, k0 = kb * 8 + t;
    float2 o;
    o.x = cvtf(W[(size_t)k0 * N + n]);
    o.y = cvtf(W[(size_t)(k0 + 4) * N + n]);
    reinterpret_cast<float2*>(dst)[q] = o;
}

// ---------------------------------------------------------------------------
// Attention prep: qkv (tf32-rounded) -> per-(b,h) fragment arrays.
// ---------------------------------------------------------------------------
__global__ void prep_qf(const float* __restrict__ qkv, float* __restrict__ Qf) {
    int gid = blockIdx.x * blockDim.x + threadIdx.x;
    if (gid >= 32 * 128 * 8 * 32) return;
    int lane = gid & 31, kk = (gid >> 5) & 7, tb = (gid >> 8) & 127, bh = gid >> 15;
    int g = lane >> 2, t = lane & 3;
    int b = bh >> 4, h = bh & 15;
    size_t base = (size_t)(b * T_ + tb * 16 + g) * QKV_N + h * 64;
    int c = kk * 8 + t;
    float4 o;
    o.x = qkv[base + c] * 0.125f;
    o.y = qkv[base + (size_t)8 * QKV_N + c] * 0.125f;
    o.z = qkv[base + c + 4] * 0.125f;
    o.w = qkv[base + (size_t)8 * QKV_N + c + 4] * 0.125f;
    reinterpret_cast<float4*>(Qf)[gid] = o;
}

__global__ void prep_kf(const float* __restrict__ qkv, float* __restrict__ Kf) {
    int gid = blockIdx.x * blockDim.x + threadIdx.x;
    if (gid >= 32 * 32 * 8 * 8 * 32) return;
    int lane = gid & 31, kk = (gid >> 5) & 7, n = (gid >> 8) & 7;
    int kt = (gid >> 11) & 31, bh = gid >> 16;
    int g = lane >> 2, t = lane & 3;
    int b = bh >> 4, h = bh & 15;
    int token = kt * 64 + n * 8 + g;
    size_t base = (size_t)(b * T_ + token) * QKV_N + C_ + h * 64;
    int c = kk * 8 + t;
    float2 o = { qkv[base + c], qkv[base + c + 4] };
    reinterpret_cast<float2*>(Kf)[gid] = o;
}

__global__ void prep_vf(const float* __restrict__ qkv, float* __restrict__ Vf) {
    int gid = blockIdx.x * blockDim.x + threadIdx.x;
    if (gid >= 32 * 32 * 8 * 8 * 32) return;
    int lane = gid & 31, kk = (gid >> 5) & 7, d = (gid >> 8) & 7;
    int kt = (gid >> 11) & 31, bh = gid >> 16;
    int g = lane >> 2, t = lane & 3;
    int b = bh >> 4, h = bh & 15;
    int token = kt * 64 + kk * 8 + t;
    size_t base = (size_t)(b * T_ + token) * QKV_N + 2 * C_ + h * 64;
    int c = d * 8 + g;
    float2 o = { qkv[base + c], qkv[base + (size_t)4 * QKV_N + c] };
    reinterpret_cast<float2*>(Vf)[gid] = o;
}

// ---------------------------------------------------------------------------
// Fragment-order tf32 GEMM, BK=32 (32 k-iterations, 3-stage cp.async).
// BM=BN=128; 256 thr = 8 warps (2x4); warp tile 64x32 (4x4 m16n8k8).
// ---------------------------------------------------------------------------
#define STAGE_FLOATS 8192                 // A 4096 + B 4096 (BK=32)
#define GSTG 3
#define GEMM_SMEM (GSTG * STAGE_FLOATS * 4)   // 96 KB

__global__ __launch_bounds__(256, 2) void gemm_frag_kernel(
        const float* __restrict__ A, const float* __restrict__ Bf,
        const float* __restrict__ bias, float* __restrict__ Cm,
        int N, int roundOut) {
    extern __shared__ float gsm[];

    const int tid  = threadIdx.x;
    const int lane = tid & 31;
    const int warp = tid >> 5;
    const int warpRow = warp >> 2;
    const int warpCol = warp & 3;
    const int g = lane >> 2, t = lane & 3;

    const int rb0 = blockIdx.y * 8;
    const int cb0 = blockIdx.x * 16;

    auto issue = [&](int s, int j) {      // j = k-iter (32 total), kb0 = 4j
        float* As = gsm + s * STAGE_FLOATS;
        float* Bs = As + 4096;
        int kb0 = j * 4;
        #pragma unroll
        for (int i = 0; i < 4; i++) {
            int idx = tid + i * 256;                    // 0..1023
            {   // A: 32 chunks (rb*4+kb) of 32 float4
                int chunk = idx >> 5, g32 = idx & 31;
                int rb = chunk >> 2, kb = chunk & 3;
                CP_ASYNC16(smem_u32(&As[(chunk * 32 + g32) * 4]),
                           &A[(((size_t)(rb0 + rb) * KB_ + kb0 + kb) * 32 + g32) * 4]);
            }
            {   // B: 64 chunks (cb*4+kb) of 16 float4
                int chunk = idx >> 4, g16 = idx & 15;
                int cb = chunk >> 2, kb = chunk & 3;
                CP_ASYNC16(smem_u32(&Bs[(chunk * 16 + g16) * 4]),
                           &Bf[(((size_t)(cb0 + cb) * KB_ + kb0 + kb) * 16 + g16) * 4]);
            }
        }
    };

    float acc[4][4][4];
    #pragma unroll
    for (int i = 0; i < 4; i++)
        #pragma unroll
        for (int j = 0; j < 4; j++)
            #pragma unroll
            for (int r = 0; r < 4; r++) acc[i][j][r] = 0.f;

    issue(0, 0); CP_COMMIT();
    issue(1, 1); CP_COMMIT();

    const int nIter = K_ / 32;            // 32
    for (int it = 0; it < nIter; it++) {
        CP_WAIT1();
        __syncthreads();
        if (it + 2 < nIter) issue((it + 2) % GSTG, it + 2);
        CP_COMMIT();

        const float* As = gsm + (it % GSTG) * STAGE_FLOATS;
        const float* Bs = As + 4096;

        #pragma unroll
        for (int ks = 0; ks < 4; ks++) {
            unsigned a[4][4];
            #pragma unroll
            for (int mt = 0; mt < 4; mt++) {
                int rb = warpRow * 4 + mt;
                float4 av = *reinterpret_cast<const float4*>(
                    &As[((rb * 4 + ks) * 32 + lane) * 4]);
                a[mt][0] = __float_as_uint(av.x);
                a[mt][1] = __float_as_uint(av.y);
                a[mt][2] = __float_as_uint(av.z);
                a[mt][3] = __float_as_uint(av.w);
            }
            unsigned b[4][2];
            #pragma unroll
            for (int nt = 0; nt < 4; nt++) {
                int cb = warpCol * 4 + nt;
                float2 bv = *reinterpret_cast<const float2*>(
                    &Bs[(cb * 4 + ks) * 64 + g * 8 + t * 2]);
                b[nt][0] = __float_as_uint(bv.x);
                b[nt][1] = __float_as_uint(bv.y);
            }
            #pragma unroll
            for (int mt = 0; mt < 4; mt++)
                #pragma unroll
                for (int nt = 0; nt < 4; nt++)
                    MMA_TF32(acc[mt][nt], a[mt][0], a[mt][1], a[mt][2], a[mt][3],
                             b[nt][0], b[nt][1]);
        }
    }

    #pragma unroll
    for (int mt = 0; mt < 4; mt++) {
        int m0 = rb0 * 16 + warpRow * 64 + mt * 16 + g;
        #pragma unroll
        for (int nt = 0; nt < 4; nt++) {
            int n0 = cb0 * 8 + warpCol * 32 + nt * 8 + t * 2;
            float v0 = acc[mt][nt][0] + bias[n0];
            float v1 = acc[mt][nt][1] + bias[n0 + 1];
            float v2 = acc[mt][nt][2] + bias[n0];
            float v3 = acc[mt][nt][3] + bias[n0 + 1];
            if (roundOut) { v0 = cvtf(v0); v1 = cvtf(v1); v2 = cvtf(v2); v3 = cvtf(v3); }
            Cm[(size_t)m0 * N + n0    ] = v0;
            Cm[(size_t)m0 * N + n0 + 1] = v1;
            Cm[(size_t)(m0 + 8) * N + n0    ] = v2;
            Cm[(size_t)(m0 + 8) * N + n0 + 1] = v3;
        }
    }
}

// ---------------------------------------------------------------------------
// Attention v3: fragment-order Q/K/V, Q in regs, cp.async double buffer,
// heavy-first block order, epilogue writes proj A-fragments directly.
// ---------------------------------------------------------------------------
#define ATT_STAGE 8192
#define ATT_PS (16 * 68)
#define ATT_SMEM ((2 * ATT_STAGE + 8 * ATT_PS) * 4)

__global__ __launch_bounds__(256, 2) void attn_v3_kernel(
        const float* __restrict__ Qf, const float* __restrict__ Kf,
        const float* __restrict__ Vf, float* __restrict__ af) {
    int qt = (gridDim.x - 1) - blockIdx.x;    // heavy blocks first
    int h  = blockIdx.y;
    int b  = blockIdx.z;
    int bh = b * H_ + h;

    extern __shared__ float asm_[];

    const int tid  = threadIdx.x;
    const int lane = tid & 31;
    const int warp = tid >> 5;
    const int g = lane >> 2, t = lane & 3;
    const int m0 = warp * 16;
    const int q0 = qt * 128;

    unsigned q[8][4];
    {
        const float4* qsrc = reinterpret_cast<const float4*>(Qf)
                           + ((size_t)bh * 128 + qt * 8 + warp) * 256;
        #pragma unroll
        for (int kk = 0; kk < 8; kk++) {
            float4 v = qsrc[kk * 32 + lane];
            q[kk][0] = __float_as_uint(v.x);
            q[kk][1] = __float_as_uint(v.y);
            q[kk][2] = __float_as_uint(v.z);
            q[kk][3] = __float_as_uint(v.w);
        }
    }

    float o[8][4];
    #pragma unroll
    for (int d = 0; d < 8; d++)
        #pragma unroll
        for (int r = 0; r < 4; r++) o[d][r] = 0.f;
    float mRow[2] = {-INFINITY, -INFINITY};
    float lRow[2] = {0.f, 0.f};

    auto issue = [&](int s, int kt) {
        const float4* ks = reinterpret_cast<const float4*>(Kf)
                         + ((size_t)bh * 32 + kt) * 1024;
        const float4* vs = reinterpret_cast<const float4*>(Vf)
                         + ((size_t)bh * 32 + kt) * 1024;
        unsigned dK = smem_u32(asm_ + s * ATT_STAGE);
        unsigned dV = dK + 4096 * 4;
        #pragma unroll
        for (int i = 0; i < 4; i++) {
            int idx = tid + i * 256;
            CP_ASYNC16(dK + idx * 16, ks + idx);
            CP_ASYNC16(dV + idx * 16, vs + idx);
        }
    };

    const int ktMax = 2 * qt + 1;
    issue(0, 0); CP_COMMIT();

    for (int kt = 0; kt <= ktMax; kt++) {
        if (kt < ktMax) issue((kt + 1) & 1, kt + 1);
        CP_COMMIT();
        CP_WAIT1();
        __syncthreads();

        int k0 = kt * 64;
        if (k0 <= q0 + m0 + 15) {
            const float* Ksm = asm_ + (kt & 1) * ATT_STAGE;
            const float* Vsm = Ksm + 4096;
            float* Psw = asm_ + 2 * ATT_STAGE + warp * ATT_PS;

            float s[8][4];
            #pragma unroll
            for (int n = 0; n < 8; n++)
                #pragma unroll
                for (int r = 0; r < 4; r++) s[n][r] = 0.f;

            #pragma unroll
            for (int kk = 0; kk < 8; kk++) {
                #pragma unroll
                for (int n = 0; n < 8; n++) {
                    float2 bv = *reinterpret_cast<const float2*>(
                        &Ksm[((n * 8 + kk) * 32 + lane) * 2]);
                    MMA_TF32(s[n], q[kk][0], q[kk][1], q[kk][2], q[kk][3],
                             __float_as_uint(bv.x), __float_as_uint(bv.y));
                }
            }

            if (k0 + 63 > q0 + m0) {
                int r0 = q0 + m0 + g, r1 = r0 + 8;
                #pragma unroll
                for (int n = 0; n < 8; n++) {
                    int c0 = k0 + n * 8 + 2 * t;
                    if (c0     > r0) s[n][0] = -INFINITY;
                    if (c0 + 1 > r0) s[n][1] = -INFINITY;
                    if (c0     > r1) s[n][2] = -INFINITY;
                    if (c0 + 1 > r1) s[n][3] = -INFINITY;
                }
            }

            #pragma unroll
            for (int half = 0; half < 2; half++) {
                float pm = -INFINITY;
                #pragma unroll
                for (int n = 0; n < 8; n++) {
                    pm = fmaxf(pm, s[n][2 * half]);
                    pm = fmaxf(pm, s[n][2 * half + 1]);
                }
                pm = fmaxf(pm, __shfl_xor_sync(0xffffffff, pm, 1));
                pm = fmaxf(pm, __shfl_xor_sync(0xffffffff, pm, 2));

                float mNew = fmaxf(mRow[half], pm);
                float alpha = __expf(mRow[half] - mNew);
                float lsum = 0.f;
                #pragma unroll
                for (int n = 0; n < 8; n++) {
                    float p0 = __expf(s[n][2 * half    ] - mNew);
                    float p1 = __expf(s[n][2 * half + 1] - mNew);
                    s[n][2 * half    ] = p0;
                    s[n][2 * half + 1] = p1;
                    lsum += p0 + p1;
                }
                lsum += __shfl_xor_sync(0xffffffff, lsum, 1);
                lsum += __shfl_xor_sync(0xffffffff, lsum, 2);
                mRow[half] = mNew;
                lRow[half] = lRow[half] * alpha + lsum;
                #pragma unroll
                for (int n = 0; n < 8; n++) {
                    o[n][2 * half    ] *= alpha;
                    o[n][2 * half + 1] *= alpha;
                }
            }

            #pragma unroll
            for (int n = 0; n < 8; n++) {
                int c = n * 8 + 2 * t;
                float2 lo = { __uint_as_float(f2tf32(s[n][0])),
                              __uint_as_float(f2tf32(s[n][1])) };
                float2 hi = { __uint_as_float(f2tf32(s[n][2])),
                              __uint_as_float(f2tf32(s[n][3])) };
                *reinterpret_cast<float2*>(&Psw[g * 68 + c])       = lo;
                *reinterpret_cast<float2*>(&Psw[(g + 8) * 68 + c]) = hi;
            }
            __syncwarp();

            #pragma unroll
            for (int kk = 0; kk < 8; kk++) {
                unsigned a0 = __float_as_uint(Psw[g * 68       + kk * 8 + t    ]);
                unsigned a1 = __float_as_uint(Psw[(g + 8) * 68 + kk * 8 + t    ]);
                unsigned a2 = __float_as_uint(Psw[g * 68       + kk * 8 + t + 4]);
                unsigned a3 = __float_as_uint(Psw[(g + 8) * 68 + kk * 8 + t + 4]);
                #pragma unroll
                for (int d = 0; d < 8; d++) {
                    float2 bv = *reinterpret_cast<const float2*>(
                        &Vsm[((d * 8 + kk) * 32 + lane) * 2]);
                    MMA_TF32(o[d], a0, a1, a2, a3,
                             __float_as_uint(bv.x), __float_as_uint(bv.y));
                }
            }
        }
        __syncthreads();
    }

    // ---- epilogue: write proj A-fragments directly (cvtf'd, scattered) ----
    // A-frag float addr(row,col) = ((rbG*KB_ + kb)*32 + g*4 + (cr&3))*4
    //                              + half + 2*(cr>>2),  cr = col%8
    {
        int rbG = b * 128 + qt * 8 + warp;     // global 16-row block
        #pragma unroll
        for (int half = 0; half < 2; half++) {
            float inv = 1.0f / lRow[half];
            #pragma unroll
            for (int d = 0; d < 8; d++) {
                int kb = h * 8 + d;
                size_t basef = (((size_t)rbG * KB_ + kb) * 32 + g * 4);
                int cr0 = 2 * t, cr1 = 2 * t + 1;
                af[(basef + (cr0 & 3)) * 4 + half + 2 * (cr0 >> 2)] =
                    cvtf(o[d][2 * half    ] * inv);
                af[(basef + (cr1 & 3)) * 4 + half + 2 * (cr1 >> 2)] =
                    cvtf(o[d][2 * half + 1] * inv);
            }
        }
    }
}

// ---------------------------------------------------------------------------
extern "C" void kernel_launch(void* const* d_in, const int* in_sizes, int n_in,
                              void* d_out, int out_size) {
    const float* x     = (const float*)d_in[0];
    const float* Wqkv  = (const float*)d_in[1];
    const float* bqkv  = (const float*)d_in[2];
    const float* Wproj = (const float*)d_in[3];
    const float* bproj = (const float*)d_in[4];
    float* out = (float*)d_out;

    float *qkv, *af, *wqkvF, *wprojF, *Qf, *Kf, *Vf;
    cudaGetSymbolAddress((void**)&qkv,    g_qkv);
    cudaGetSymbolAddress((void**)&af,     g_af);
    cudaGetSymbolAddress((void**)&wqkvF,  g_wqkvF);
    cudaGetSymbolAddress((void**)&wprojF, g_wprojF);
    cudaGetSymbolAddress((void**)&Qf,     g_Qf);
    cudaGetSymbolAddress((void**)&Kf,     g_Kf);
    cudaGetSymbolAddress((void**)&Vf,     g_Vf);

    cudaFuncSetAttribute(gemm_frag_kernel,
                         cudaFuncAttributeMaxDynamicSharedMemorySize, GEMM_SMEM);
    cudaFuncSetAttribute(attn_v3_kernel,
                         cudaFuncAttributeMaxDynamicSharedMemorySize, ATT_SMEM);

    // 0) GEMM input prep
    prep_a_frag<<<(M_ * K_ / 4) / 256, 256>>>(x, af);
    prep_b_frag<<<(QKV_N * K_ / 2) / 256, 256>>>(Wqkv, wqkvF, QKV_N);
    prep_b_frag<<<(C_ * K_ / 2) / 256, 256>>>(Wproj, wprojF, C_);

    // 1) QKV projection (tf32-rounded output)
    {
        dim3 grid(QKV_N / 128, M_ / 128);
        gemm_frag_kernel<<<grid, 256, GEMM_SMEM>>>(af, wqkvF, bqkv, qkv, QKV_N, 1);
    }

    // 2) attention prep: Q/K/V fragment arrays
    prep_qf<<<(32 * 128 * 8 * 32) / 256, 256>>>(qkv, Qf);
    prep_kf<<<(32 * 32 * 8 * 8 * 32) / 256, 256>>>(qkv, Kf);
    prep_vf<<<(32 * 32 * 8 * 8 * 32) / 256, 256>>>(qkv, Vf);

    // 3) causal flash attention (writes proj A-fragments directly)
    {
        dim3 grid(T_ / 128, H_, B_);
        attn_v3_kernel<<<grid, 256, ATT_SMEM>>>(Qf, Kf, Vf, af);
    }

    // 4) output projection (full fp32 out)
    {
        dim3 grid(C_ / 128, M_ / 128);
        gemm_frag_kernel<<<grid, 256, GEMM_SMEM>>>(af, wprojF, bproj, out, C_, 0);
    }
}

// round 16
// speedup vs baseline: 1.5138x; 1.0257x over previous
#include <cuda_runtime.h>
#include <math.h>

// Problem constants
#define B_  2
#define T_  2048
#define C_  1024
#define H_  16
#define D_  64
#define M_  4096             // B*T
#define QKV_N 3072
#define K_  1024
#define KB_ (K_ / 8)         // 128 k-blocks of 8

// Scratch (allocation-free rule: __device__ globals)
__device__ float g_af[(size_t)M_ * C_];        // A-fragments (x, then O)
__device__ float g_wqkvF[(size_t)K_ * QKV_N];  // B-fragments of W_qkv
__device__ float g_wprojF[(size_t)K_ * C_];    // B-fragments of W_proj
__device__ float g_Qf[(size_t)M_ * C_];        // Q fragments (scaled)
__device__ float g_Kf[(size_t)M_ * C_];        // K fragments
__device__ float g_Vf[(size_t)M_ * C_];        // V fragments

// ---------------------------------------------------------------------------
__device__ __forceinline__ unsigned f2tf32(float f) {
    unsigned u;
    asm("cvt.rna.tf32.f32 %0, %1;" : "=r"(u) : "f"(f));
    return u;
}
__device__ __forceinline__ float cvtf(float v) {
    return __uint_as_float(f2tf32(v));
}
__device__ __forceinline__ unsigned smem_u32(const void* p) {
    return (unsigned)__cvta_generic_to_shared(p);
}
#define CP_ASYNC16(dst, src) \
    asm volatile("cp.async.cg.shared.global [%0], [%1], 16;" \
                 :: "r"(dst), "l"(src))
#define CP_COMMIT()  asm volatile("cp.async.commit_group;")
#define CP_WAIT1()   asm volatile("cp.async.wait_group 1;")

#define MMA_TF32(acc, a0, a1, a2, a3, b0, b1) \
    asm volatile( \
        "mma.sync.aligned.m16n8k8.row.col.f32.tf32.tf32.f32 " \
        "{%0,%1,%2,%3},{%4,%5,%6,%7},{%8,%9},{%0,%1,%2,%3};" \
        : "+f"((acc)[0]), "+f"((acc)[1]), "+f"((acc)[2]), "+f"((acc)[3]) \
        : "r"(a0), "r"(a1), "r"(a2), "r"(a3), "r"(b0), "r"(b1))

// ---------------------------------------------------------------------------
// GEMM prep: row-major -> fragment order (tf32).
// ---------------------------------------------------------------------------
__global__ void prep_a_frag(const float* __restrict__ src, float* __restrict__ dst) {
    int q = blockIdx.x * blockDim.x + threadIdx.x;
    if (q >= M_ * K_ / 4) return;
    int l = q & 31;
    int rk = q >> 5;
    int kb = rk % KB_, rb = rk / KB_;
    int g = l >> 2, t = l & 3;
    int r0 = rb * 16 + g, c0 = kb * 8 + t;
    float4 o;
    o.x = cvtf(src[(size_t)r0 * K_ + c0]);
    o.y = cvtf(src[(size_t)(r0 + 8) * K_ + c0]);
    o.z = cvtf(src[(size_t)r0 * K_ + c0 + 4]);
    o.w = cvtf(src[(size_t)(r0 + 8) * K_ + c0 + 4]);
    reinterpret_cast<float4*>(dst)[q] = o;
}

__global__ void prep_b_frag(const float* __restrict__ W, float* __restrict__ dst, int N) {
    int q = blockIdx.x * blockDim.x + threadIdx.x;
    if (q >= N * K_ / 2) return;
    int l = q & 31;
    int ck = q >> 5;
    int kb = ck % KB_, cb = ck / KB_;
    int g = l >> 2, t = l & 3;
    int n = cb * 8 + g, k0 = kb * 8 + t;
    float2 o;
    o.x = cvtf(W[(size_t)k0 * N + n]);
    o.y = cvtf(W[(size_t)(k0 + 4) * N + n]);
    reinterpret_cast<float2*>(dst)[q] = o;
}

// ---------------------------------------------------------------------------
// Fragment-order tf32 GEMM, BK=32 (32 k-iterations, 3-stage cp.async).
// BM=BN=128; 256 thr = 8 warps (2x4); warp tile 64x32 (4x4 m16n8k8).
// mode 0: Cm = acc + bias (fp32, row-major)
// mode 1: QKV fused epilogue -> scatter cvtf(acc+bias) into Qf/Kf/Vf
//         fragment arrays (Q scaled by 0.125).
// ---------------------------------------------------------------------------
#define STAGE_FLOATS 8192                 // A 4096 + B 4096 (BK=32)
#define GSTG 3
#define GEMM_SMEM (GSTG * STAGE_FLOATS * 4)   // 96 KB

__global__ __launch_bounds__(256, 2) void gemm_frag_kernel(
        const float* __restrict__ A, const float* __restrict__ Bf,
        const float* __restrict__ bias, float* __restrict__ Cm,
        float* __restrict__ Qf, float* __restrict__ Kf, float* __restrict__ Vf,
        int N, int mode) {
    extern __shared__ float gsm[];

    const int tid  = threadIdx.x;
    const int lane = tid & 31;
    const int warp = tid >> 5;
    const int warpRow = warp >> 2;
    const int warpCol = warp & 3;
    const int g = lane >> 2, t = lane & 3;

    const int rb0 = blockIdx.y * 8;
    const int cb0 = blockIdx.x * 16;

    auto issue = [&](int s, int j) {
        float* As = gsm + s * STAGE_FLOATS;
        float* Bs = As + 4096;
        int kb0 = j * 4;
        #pragma unroll
        for (int i = 0; i < 4; i++) {
            int idx = tid + i * 256;
            {
                int chunk = idx >> 5, g32 = idx & 31;
                int rb = chunk >> 2, kb = chunk & 3;
                CP_ASYNC16(smem_u32(&As[(chunk * 32 + g32) * 4]),
                           &A[(((size_t)(rb0 + rb) * KB_ + kb0 + kb) * 32 + g32) * 4]);
            }
            {
                int chunk = idx >> 4, g16 = idx & 15;
                int cb = chunk >> 2, kb = chunk & 3;
                CP_ASYNC16(smem_u32(&Bs[(chunk * 16 + g16) * 4]),
                           &Bf[(((size_t)(cb0 + cb) * KB_ + kb0 + kb) * 16 + g16) * 4]);
            }
        }
    };

    float acc[4][4][4];
    #pragma unroll
    for (int i = 0; i < 4; i++)
        #pragma unroll
        for (int j = 0; j < 4; j++)
            #pragma unroll
            for (int r = 0; r < 4; r++) acc[i][j][r] = 0.f;

    issue(0, 0); CP_COMMIT();
    issue(1, 1); CP_COMMIT();

    const int nIter = K_ / 32;
    for (int it = 0; it < nIter; it++) {
        CP_WAIT1();
        __syncthreads();
        if (it + 2 < nIter) issue((it + 2) % GSTG, it + 2);
        CP_COMMIT();

        const float* As = gsm + (it % GSTG) * STAGE_FLOATS;
        const float* Bs = As + 4096;

        #pragma unroll
        for (int ks = 0; ks < 4; ks++) {
            unsigned a[4][4];
            #pragma unroll
            for (int mt = 0; mt < 4; mt++) {
                int rb = warpRow * 4 + mt;
                float4 av = *reinterpret_cast<const float4*>(
                    &As[((rb * 4 + ks) * 32 + lane) * 4]);
                a[mt][0] = __float_as_uint(av.x);
                a[mt][1] = __float_as_uint(av.y);
                a[mt][2] = __float_as_uint(av.z);
                a[mt][3] = __float_as_uint(av.w);
            }
            unsigned b[4][2];
            #pragma unroll
            for (int nt = 0; nt < 4; nt++) {
                int cb = warpCol * 4 + nt;
                float2 bv = *reinterpret_cast<const float2*>(
                    &Bs[(cb * 4 + ks) * 64 + g * 8 + t * 2]);
                b[nt][0] = __float_as_uint(bv.x);
                b[nt][1] = __float_as_uint(bv.y);
            }
            #pragma unroll
            for (int mt = 0; mt < 4; mt++)
                #pragma unroll
                for (int nt = 0; nt < 4; nt++)
                    MMA_TF32(acc[mt][nt], a[mt][0], a[mt][1], a[mt][2], a[mt][3],
                             b[nt][0], b[nt][1]);
        }
    }

    if (mode == 0) {
        #pragma unroll
        for (int mt = 0; mt < 4; mt++) {
            int m0 = rb0 * 16 + warpRow * 64 + mt * 16 + g;
            #pragma unroll
            for (int nt = 0; nt < 4; nt++) {
                int n0 = cb0 * 8 + warpCol * 32 + nt * 8 + t * 2;
                Cm[(size_t)m0 * N + n0    ] = acc[mt][nt][0] + bias[n0];
                Cm[(size_t)m0 * N + n0 + 1] = acc[mt][nt][1] + bias[n0 + 1];
                Cm[(size_t)(m0 + 8) * N + n0    ] = acc[mt][nt][2] + bias[n0];
                Cm[(size_t)(m0 + 8) * N + n0 + 1] = acc[mt][nt][3] + bias[n0 + 1];
            }
        }
    } else {
        // QKV fused epilogue: scatter into fragment arrays.
        // Section is uniform per block (128-col tiles don't straddle Q/K/V).
        const int sec = (cb0 * 8) >> 10;
        #pragma unroll
        for (int mt = 0; mt < 4; mt++) {
            #pragma unroll
            for (int nt = 0; nt < 4; nt++) {
                #pragma unroll
                for (int r = 0; r < 4; r++) {
                    int row = rb0 * 16 + warpRow * 64 + mt * 16 + g
                            + ((r >> 1) << 3);
                    int col = cb0 * 8 + warpCol * 32 + nt * 8 + t * 2 + (r & 1);
                    float v = cvtf(acc[mt][nt][r] + bias[col]);
                    int bb = row >> 11, tp = row & 2047;
                    int hc = col & 1023, h = hc >> 6, c = hc & 63;
                    int bh = bb * 16 + h;
                    if (sec == 0) {
                        int tb = tp >> 4, g2 = tp & 7, rh = (tp >> 3) & 1;
                        int kk = c >> 3, cl = c & 7;
                        size_t addr =
                            ((((size_t)bh * 128 + tb) * 8 + kk) * 32
                             + g2 * 4 + (cl & 3)) * 4 + rh + 2 * (cl >> 2);
                        Qf[addr] = v * 0.125f;
                    } else if (sec == 1) {
                        int kt = tp >> 6, n8 = (tp >> 3) & 7, g2 = tp & 7;
                        int kk = c >> 3, cl = c & 7;
                        size_t addr =
                            (((((size_t)bh * 32 + kt) * 8 + n8) * 8 + kk) * 32
                             + g2 * 4 + (cl & 3)) * 2 + (cl >> 2);
                        Kf[addr] = v;
                    } else {
                        int kt = tp >> 6, kkv = (tp >> 3) & 7;
                        int tsv = tp & 3, th = (tp >> 2) & 1;
                        int d = c >> 3, g2 = c & 7;
                        size_t addr =
                            (((((size_t)bh * 32 + kt) * 8 + d) * 8 + kkv) * 32
                             + g2 * 4 + tsv) * 2 + th;
                        Vf[addr] = v;
                    }
                }
            }
        }
    }
}

// ---------------------------------------------------------------------------
// Attention v3: fragment-order Q/K/V, Q in regs, cp.async double buffer,
// heavy-first block order, epilogue writes proj A-fragments directly.
// ---------------------------------------------------------------------------
#define ATT_STAGE 8192
#define ATT_PS (16 * 68)
#define ATT_SMEM ((2 * ATT_STAGE + 8 * ATT_PS) * 4)

__global__ __launch_bounds__(256, 2) void attn_v3_kernel(
        const float* __restrict__ Qf, const float* __restrict__ Kf,
        const float* __restrict__ Vf, float* __restrict__ af) {
    int qt = (gridDim.x - 1) - blockIdx.x;    // heavy blocks first
    int h  = blockIdx.y;
    int b  = blockIdx.z;
    int bh = b * H_ + h;

    extern __shared__ float asm_[];

    const int tid  = threadIdx.x;
    const int lane = tid & 31;
    const int warp = tid >> 5;
    const int g = lane >> 2, t = lane & 3;
    const int m0 = warp * 16;
    const int q0 = qt * 128;

    unsigned q[8][4];
    {
        const float4* qsrc = reinterpret_cast<const float4*>(Qf)
                           + ((size_t)bh * 128 + qt * 8 + warp) * 256;
        #pragma unroll
        for (int kk = 0; kk < 8; kk++) {
            float4 v = qsrc[kk * 32 + lane];
            q[kk][0] = __float_as_uint(v.x);
            q[kk][1] = __float_as_uint(v.y);
            q[kk][2] = __float_as_uint(v.z);
            q[kk][3] = __float_as_uint(v.w);
        }
    }

    float o[8][4];
    #pragma unroll
    for (int d = 0; d < 8; d++)
        #pragma unroll
        for (int r = 0; r < 4; r++) o[d][r] = 0.f;
    float mRow[2] = {-INFINITY, -INFINITY};
    float lRow[2] = {0.f, 0.f};

    auto issue = [&](int s, int kt) {
        const float4* ks = reinterpret_cast<const float4*>(Kf)
                         + ((size_t)bh * 32 + kt) * 1024;
        const float4* vs = reinterpret_cast<const float4*>(Vf)
                         + ((size_t)bh * 32 + kt) * 1024;
        unsigned dK = smem_u32(asm_ + s * ATT_STAGE);
        unsigned dV = dK + 4096 * 4;
        #pragma unroll
        for (int i = 0; i < 4; i++) {
            int idx = tid + i * 256;
            CP_ASYNC16(dK + idx * 16, ks + idx);
            CP_ASYNC16(dV + idx * 16, vs + idx);
        }
    };

    const int ktMax = 2 * qt + 1;
    issue(0, 0); CP_COMMIT();

    for (int kt = 0; kt <= ktMax; kt++) {
        if (kt < ktMax) issue((kt + 1) & 1, kt + 1);
        CP_COMMIT();
        CP_WAIT1();
        __syncthreads();

        int k0 = kt * 64;
        if (k0 <= q0 + m0 + 15) {
            const float* Ksm = asm_ + (kt & 1) * ATT_STAGE;
            const float* Vsm = Ksm + 4096;
            float* Psw = asm_ + 2 * ATT_STAGE + warp * ATT_PS;

            float s[8][4];
            #pragma unroll
            for (int n = 0; n < 8; n++)
                #pragma unroll
                for (int r = 0; r < 4; r++) s[n][r] = 0.f;

            #pragma unroll
            for (int kk = 0; kk < 8; kk++) {
                #pragma unroll
                for (int n = 0; n < 8; n++) {
                    float2 bv = *reinterpret_cast<const float2*>(
                        &Ksm[((n * 8 + kk) * 32 + lane) * 2]);
                    MMA_TF32(s[n], q[kk][0], q[kk][1], q[kk][2], q[kk][3],
                             __float_as_uint(bv.x), __float_as_uint(bv.y));
                }
            }

            if (k0 + 63 > q0 + m0) {
                int r0 = q0 + m0 + g, r1 = r0 + 8;
                #pragma unroll
                for (int n = 0; n < 8; n++) {
                    int c0 = k0 + n * 8 + 2 * t;
                    if (c0     > r0) s[n][0] = -INFINITY;
                    if (c0 + 1 > r0) s[n][1] = -INFINITY;
                    if (c0     > r1) s[n][2] = -INFINITY;
                    if (c0 + 1 > r1) s[n][3] = -INFINITY;
                }
            }

            #pragma unroll
            for (int half = 0; half < 2; half++) {
                float pm = -INFINITY;
                #pragma unroll
                for (int n = 0; n < 8; n++) {
                    pm = fmaxf(pm, s[n][2 * half]);
                    pm = fmaxf(pm, s[n][2 * half + 1]);
                }
                pm = fmaxf(pm, __shfl_xor_sync(0xffffffff, pm, 1));
                pm = fmaxf(pm, __shfl_xor_sync(0xffffffff, pm, 2));

                float mNew = fmaxf(mRow[half], pm);
                float alpha = __expf(mRow[half] - mNew);
                float lsum = 0.f;
                #pragma unroll
                for (int n = 0; n < 8; n++) {
                    float p0 = __expf(s[n][2 * half    ] - mNew);
                    float p1 = __expf(s[n][2 * half + 1] - mNew);
                    s[n][2 * half    ] = p0;
                    s[n][2 * half + 1] = p1;
                    lsum += p0 + p1;
                }
                lsum += __shfl_xor_sync(0xffffffff, lsum, 1);
                lsum += __shfl_xor_sync(0xffffffff, lsum, 2);
                mRow[half] = mNew;
                lRow[half] = lRow[half] * alpha + lsum;
                #pragma unroll
                for (int n = 0; n < 8; n++) {
                    o[n][2 * half    ] *= alpha;
                    o[n][2 * half + 1] *= alpha;
                }
            }

            #pragma unroll
            for (int n = 0; n < 8; n++) {
                int c = n * 8 + 2 * t;
                float2 lo = { __uint_as_float(f2tf32(s[n][0])),
                              __uint_as_float(f2tf32(s[n][1])) };
                float2 hi = { __uint_as_float(f2tf32(s[n][2])),
                              __uint_as_float(f2tf32(s[n][3])) };
                *reinterpret_cast<float2*>(&Psw[g * 68 + c])       = lo;
                *reinterpret_cast<float2*>(&Psw[(g + 8) * 68 + c]) = hi;
            }
            __syncwarp();

            #pragma unroll
            for (int kk = 0; kk < 8; kk++) {
                unsigned a0 = __float_as_uint(Psw[g * 68       + kk * 8 + t    ]);
                unsigned a1 = __float_as_uint(Psw[(g + 8) * 68 + kk * 8 + t    ]);
                unsigned a2 = __float_as_uint(Psw[g * 68       + kk * 8 + t + 4]);
                unsigned a3 = __float_as_uint(Psw[(g + 8) * 68 + kk * 8 + t + 4]);
                #pragma unroll
                for (int d = 0; d < 8; d++) {
                    float2 bv = *reinterpret_cast<const float2*>(
                        &Vsm[((d * 8 + kk) * 32 + lane) * 2]);
                    MMA_TF32(o[d], a0, a1, a2, a3,
                             __float_as_uint(bv.x), __float_as_uint(bv.y));
                }
            }
        }
        __syncthreads();
    }

    // ---- epilogue: write proj A-fragments directly (cvtf'd, scattered) ----
    {
        int rbG = b * 128 + qt * 8 + warp;     // global 16-row block
        #pragma unroll
        for (int half = 0; half < 2; half++) {
            float inv = 1.0f / lRow[half];
            #pragma unroll
            for (int d = 0; d < 8; d++) {
                int kb = h * 8 + d;
                size_t basef = (((size_t)rbG * KB_ + kb) * 32 + g * 4);
                int cr0 = 2 * t, cr1 = 2 * t + 1;
                af[(basef + (cr0 & 3)) * 4 + half + 2 * (cr0 >> 2)] =
                    cvtf(o[d][2 * half    ] * inv);
                af[(basef + (cr1 & 3)) * 4 + half + 2 * (cr1 >> 2)] =
                    cvtf(o[d][2 * half + 1] * inv);
            }
        }
    }
}

// ---------------------------------------------------------------------------
extern "C" void kernel_launch(void* const* d_in, const int* in_sizes, int n_in,
                              void* d_out, int out_size) {
    const float* x     = (const float*)d_in[0];
    const float* Wqkv  = (const float*)d_in[1];
    const float* bqkv  = (const float*)d_in[2];
    const float* Wproj = (const float*)d_in[3];
    const float* bproj = (const float*)d_in[4];
    float* out = (float*)d_out;

    float *af, *wqkvF, *wprojF, *Qf, *Kf, *Vf;
    cudaGetSymbolAddress((void**)&af,     g_af);
    cudaGetSymbolAddress((void**)&wqkvF,  g_wqkvF);
    cudaGetSymbolAddress((void**)&wprojF, g_wprojF);
    cudaGetSymbolAddress((void**)&Qf,     g_Qf);
    cudaGetSymbolAddress((void**)&Kf,     g_Kf);
    cudaGetSymbolAddress((void**)&Vf,     g_Vf);

    cudaFuncSetAttribute(gemm_frag_kernel,
                         cudaFuncAttributeMaxDynamicSharedMemorySize, GEMM_SMEM);
    cudaFuncSetAttribute(attn_v3_kernel,
                         cudaFuncAttributeMaxDynamicSharedMemorySize, ATT_SMEM);

    // 0) GEMM input prep
    prep_a_frag<<<(M_ * K_ / 4) / 256, 256>>>(x, af);
    prep_b_frag<<<(QKV_N * K_ / 2) / 256, 256>>>(Wqkv, wqkvF, QKV_N);
    prep_b_frag<<<(C_ * K_ / 2) / 256, 256>>>(Wproj, wprojF, C_);

    // 1) QKV projection, fused epilogue -> Qf/Kf/Vf fragment arrays
    {
        dim3 grid(QKV_N / 128, M_ / 128);
        gemm_frag_kernel<<<grid, 256, GEMM_SMEM>>>(
            af, wqkvF, bqkv, nullptr, Qf, Kf, Vf, QKV_N, 1);
    }

    // 2) causal flash attention (writes proj A-fragments directly)
    {
        dim3 grid(T_ / 128, H_, B_);
        attn_v3_kernel<<<grid, 256, ATT_SMEM>>>(Qf, Kf, Vf, af);
    }

    // 3) output projection (full fp32 out)
    {
        dim3 grid(C_ / 128, M_ / 128);
        gemm_frag_kernel<<<grid, 256, GEMM_SMEM>>>(
            af, wprojF, bproj, out, nullptr, nullptr, nullptr, C_, 0);
    }
}